// round 3
// baseline (speedup 1.0000x reference)
#include <cuda_runtime.h>

#define S_LEN 1024
#define DHDIM 64
#define NHEADS 8
#define NBATCH 4
#define BHN (NBATCH * NHEADS)
#define ATTN_SMEM (53696 * 4)

__device__ float g_Q[BHN * S_LEN * DHDIM];
__device__ float g_K[BHN * S_LEN * DHDIM];
__device__ float g_V[BHN * S_LEN * DHDIM];
__device__ float g_CTX[NBATCH * S_LEN * (NHEADS * DHDIM)];

// C[M=4096,N=512] = A[4096,512] @ W[512,512]; split_heads scatters to [B,H,S,DH]
__global__ __launch_bounds__(256, 1) void sgemm_kernel(
    const float* __restrict__ A, const float* __restrict__ W,
    float* __restrict__ C, int split_heads)
{
    const int K = 512, N = 512;
    __shared__ float As[16][128];
    __shared__ float Bs[16][128];
    const int tid = threadIdx.x;
    const int m0 = blockIdx.y * 128;
    const int n0 = blockIdx.x * 128;
    const int ty = tid >> 4, tx = tid & 15;
    const int arow = tid >> 2, acol = (tid & 3) << 2;
    const int brow = tid >> 5, bcol = (tid & 31) << 2;

    float acc[8][8];
#pragma unroll
    for (int i = 0; i < 8; i++)
#pragma unroll
        for (int j = 0; j < 8; j++) acc[i][j] = 0.f;

    for (int k0 = 0; k0 < K; k0 += 16) {
        __syncthreads();
#pragma unroll
        for (int it = 0; it < 2; it++) {
            int r = arow + it * 64;
            float4 a4 = *(const float4*)(A + (size_t)(m0 + r) * K + k0 + acol);
            As[acol + 0][r] = a4.x; As[acol + 1][r] = a4.y;
            As[acol + 2][r] = a4.z; As[acol + 3][r] = a4.w;
        }
#pragma unroll
        for (int it = 0; it < 2; it++) {
            int r = brow + it * 8;
            *(float4*)(&Bs[r][bcol]) = *(const float4*)(W + (size_t)(k0 + r) * N + n0 + bcol);
        }
        __syncthreads();
#pragma unroll
        for (int kk = 0; kk < 16; kk++) {
            float af[8], bf[8];
            *(float4*)(af)     = *(float4*)(&As[kk][ty * 8]);
            *(float4*)(af + 4) = *(float4*)(&As[kk][ty * 8 + 4]);
            *(float4*)(bf)     = *(float4*)(&Bs[kk][tx * 8]);
            *(float4*)(bf + 4) = *(float4*)(&Bs[kk][tx * 8 + 4]);
#pragma unroll
            for (int i = 0; i < 8; i++)
#pragma unroll
                for (int j = 0; j < 8; j++) acc[i][j] += af[i] * bf[j];
        }
    }
#pragma unroll
    for (int i = 0; i < 8; i++) {
        int m = m0 + ty * 8 + i;
#pragma unroll
        for (int j4 = 0; j4 < 2; j4++) {
            int n = n0 + tx * 8 + j4 * 4;
            float4 v = make_float4(acc[i][j4*4+0], acc[i][j4*4+1], acc[i][j4*4+2], acc[i][j4*4+3]);
            if (split_heads) {
                int b = m >> 10, s = m & 1023, h = n >> 6, dh = n & 63;
                *(float4*)(C + ((size_t)((b << 3) + h) * S_LEN + s) * DHDIM + dh) = v;
            } else {
                *(float4*)(C + (size_t)m * 512 + n) = v;
            }
        }
    }
}

// fused causal attention + skewed relative bias. BM=64, BN=128, 256 threads.
__global__ __launch_bounds__(256, 1) void attn_kernel(const float* __restrict__ rel)
{
    extern __shared__ float sm[];
    float* q_s   = sm;            // [64][64]  q_s[d*64+i]
    float* k_s   = sm + 4096;     // [64][128] k_s[d*128+t]
    float* v_s   = sm + 12288;    // [128][64]
    float* rel_s = sm + 20480;    // [64][192]
    float* qe_s  = sm + 32768;    // [64][192]
    float* s_t   = sm + 45056;    // [64][132]
    float* m_s   = sm + 53504;
    float* ls_s  = sm + 53568;
    float* al_s  = sm + 53632;

    const int tid = threadIdx.x;
    const int qi = blockIdx.x;     // 0..15
    const int bh = blockIdx.y;     // 0..31
    const int h  = bh & 7;
    const int i0 = qi * 64;
    const float* Qp = g_Q + (size_t)bh * (S_LEN * DHDIM);
    const float* Kp = g_K + (size_t)bh * (S_LEN * DHDIM);
    const float* Vp = g_V + (size_t)bh * (S_LEN * DHDIM);
    const float* Rp = rel + (size_t)h * (DHDIM * S_LEN);

#pragma unroll
    for (int it = 0; it < 4; it++) {
        int lin = tid + it * 256, row = lin >> 4, d4 = (lin & 15) << 2;
        float4 v = *(const float4*)(Qp + (size_t)(i0 + row) * DHDIM + d4);
        q_s[(d4+0)*64+row] = v.x; q_s[(d4+1)*64+row] = v.y;
        q_s[(d4+2)*64+row] = v.z; q_s[(d4+3)*64+row] = v.w;
    }
    if (tid < 64) { m_s[tid] = -3.0e38f; ls_s[tid] = 0.f; }

    const int tr = tid >> 5;   // 0..7
    const int tc = tid & 31;   // 0..31
    float acc_o[8][2];
#pragma unroll
    for (int r = 0; r < 8; r++) { acc_o[r][0] = 0.f; acc_o[r][1] = 0.f; }

    const int ntiles = (i0 + 63) / 128 + 1;
    for (int jt = 0; jt < ntiles; jt++) {
        const int j0 = jt * 128;
        const int lmin = 960 - i0 + j0;
        __syncthreads();
#pragma unroll
        for (int it = 0; it < 8; it++) {
            int lin = tid + it * 256, t = lin >> 4, d4 = (lin & 15) << 2;
            float4 v = *(const float4*)(Kp + (size_t)(j0 + t) * DHDIM + d4);
            k_s[(d4+0)*128+t] = v.x; k_s[(d4+1)*128+t] = v.y;
            k_s[(d4+2)*128+t] = v.z; k_s[(d4+3)*128+t] = v.w;
        }
#pragma unroll
        for (int it = 0; it < 8; it++) {
            int lin = tid + it * 256, t = lin >> 4, d4 = (lin & 15) << 2;
            *(float4*)(v_s + t * 64 + d4) = *(const float4*)(Vp + (size_t)(j0 + t) * DHDIM + d4);
        }
#pragma unroll
        for (int it = 0; it < 12; it++) {
            int lin = tid + it * 256;
            int d = lin / 48, x = (lin % 48) << 2, l = lmin + x;
            float4 v;
            if (l + 3 <= 1023) v = *(const float4*)(Rp + (size_t)d * S_LEN + l);
            else {
                v.x = (l   <= 1023) ? Rp[(size_t)d*S_LEN + l  ] : 0.f;
                v.y = (l+1 <= 1023) ? Rp[(size_t)d*S_LEN + l+1] : 0.f;
                v.z = (l+2 <= 1023) ? Rp[(size_t)d*S_LEN + l+2] : 0.f;
                v.w = 0.f;
            }
            *(float4*)(rel_s + d * 192 + x) = v;
        }
        __syncthreads();

        // QE band GEMM
        {
            float a2[8][6];
#pragma unroll
            for (int r = 0; r < 8; r++)
#pragma unroll
                for (int c = 0; c < 6; c++) a2[r][c] = 0.f;
            for (int d = 0; d < 64; d++) {
                float qf[8], rf[6];
                *(float4*)(qf)     = *(float4*)(q_s + d * 64 + tr * 8);
                *(float4*)(qf + 4) = *(float4*)(q_s + d * 64 + tr * 8 + 4);
                *(float2*)(rf)     = *(float2*)(rel_s + d * 192 + tc * 6);
                *(float2*)(rf + 2) = *(float2*)(rel_s + d * 192 + tc * 6 + 2);
                *(float2*)(rf + 4) = *(float2*)(rel_s + d * 192 + tc * 6 + 4);
#pragma unroll
                for (int r = 0; r < 8; r++)
#pragma unroll
                    for (int c = 0; c < 6; c++) a2[r][c] += qf[r] * rf[c];
            }
#pragma unroll
            for (int r = 0; r < 8; r++)
#pragma unroll
                for (int c = 0; c < 6; c += 2)
                    *(float2*)(qe_s + (tr*8+r)*192 + tc*6 + c) = make_float2(a2[r][c], a2[r][c+1]);
        }

        // QK^T
        float acc[8][4];
#pragma unroll
        for (int r = 0; r < 8; r++)
#pragma unroll
            for (int c = 0; c < 4; c++) acc[r][c] = 0.f;
        for (int d = 0; d < 64; d++) {
            float qf[8], kf[4];
            *(float4*)(qf)     = *(float4*)(q_s + d * 64 + tr * 8);
            *(float4*)(qf + 4) = *(float4*)(q_s + d * 64 + tr * 8 + 4);
            *(float4*)(kf)     = *(float4*)(k_s + d * 128 + tc * 4);
#pragma unroll
            for (int r = 0; r < 8; r++)
#pragma unroll
                for (int c = 0; c < 4; c++) acc[r][c] += qf[r] * kf[c];
        }
        __syncthreads();

#pragma unroll
        for (int r = 0; r < 8; r++) {
            int ii = tr * 8 + r, i = i0 + ii;
#pragma unroll
            for (int c = 0; c < 4; c++) {
                int tt = tc * 4 + c, t = j0 + tt;
                float qe = qe_s[ii * 192 + (63 - ii + tt)];
                s_t[ii * 132 + tt] = (acc[r][c] + qe + ((t > i) ? -1e9f : 0.f)) * 0.125f;
            }
        }
        __syncthreads();

        // online softmax: 4 lanes/row
        {
            int row = tid >> 2, qq = tid & 3;
            float mloc = -3.0e38f;
#pragma unroll
            for (int cc = 0; cc < 32; cc++)
                mloc = fmaxf(mloc, s_t[row * 132 + qq + (cc << 2)]);
            mloc = fmaxf(mloc, __shfl_xor_sync(0xffffffffu, mloc, 1));
            mloc = fmaxf(mloc, __shfl_xor_sync(0xffffffffu, mloc, 2));
            float mold = m_s[row];
            float mnew = fmaxf(mold, mloc);
            float suml = 0.f;
#pragma unroll
            for (int cc = 0; cc < 32; cc++) {
                int idx = row * 132 + qq + (cc << 2);
                float p = __expf(s_t[idx] - mnew);
                s_t[idx] = p;
                suml += p;
            }
            suml += __shfl_xor_sync(0xffffffffu, suml, 1);
            suml += __shfl_xor_sync(0xffffffffu, suml, 2);
            if (qq == 0) {
                float alpha = __expf(mold - mnew);
                al_s[row] = alpha;
                ls_s[row] = ls_s[row] * alpha + suml;
                m_s[row] = mnew;
            }
        }
        __syncthreads();

        // O = O*alpha + P@V
        {
#pragma unroll
            for (int r = 0; r < 8; r++) {
                float a = al_s[tr * 8 + r];
                acc_o[r][0] *= a; acc_o[r][1] *= a;
            }
            for (int t4 = 0; t4 < 32; t4++) {
                float p4[8][4];
#pragma unroll
                for (int r = 0; r < 8; r++)
                    *(float4*)(p4[r]) = *(float4*)(s_t + (tr*8+r)*132 + (t4 << 2));
#pragma unroll
                for (int u = 0; u < 4; u++) {
                    float2 vv = *(float2*)(v_s + ((t4 << 2) + u) * 64 + tc * 2);
#pragma unroll
                    for (int r = 0; r < 8; r++) {
                        acc_o[r][0] += p4[r][u] * vv.x;
                        acc_o[r][1] += p4[r][u] * vv.y;
                    }
                }
            }
        }
    }

    __syncthreads();
    int b = bh >> 3;
#pragma unroll
    for (int r = 0; r < 8; r++) {
        int ii = tr * 8 + r;
        float inv = 1.f / ls_s[ii];
        *(float2*)(g_CTX + (size_t)(b * S_LEN + i0 + ii) * 512 + h * 64 + tc * 2) =
            make_float2(acc_o[r][0] * inv, acc_o[r][1] * inv);
    }
}

extern "C" void kernel_launch(void* const* d_in, const int* in_sizes, int n_in,
                              void* d_out, int out_size)
{
    const float* queries = (const float*)d_in[0];
    const float* keys    = (const float*)d_in[1];
    const float* values  = (const float*)d_in[2];
    // d_in[3] = mask: causal, folded analytically
    const float* Wq = (const float*)d_in[4];
    const float* Wk = (const float*)d_in[5];
    const float* Wv = (const float*)d_in[6];
    const float* Wo = (const float*)d_in[7];
    const float* rel = (const float*)d_in[8];
    float* out = (float*)d_out;

    float *pQ, *pK, *pV, *pC;
    cudaGetSymbolAddress((void**)&pQ, g_Q);
    cudaGetSymbolAddress((void**)&pK, g_K);
    cudaGetSymbolAddress((void**)&pV, g_V);
    cudaGetSymbolAddress((void**)&pC, g_CTX);

    cudaFuncSetAttribute(attn_kernel, cudaFuncAttributeMaxDynamicSharedMemorySize, ATTN_SMEM);

    dim3 gg(4, 32), tb(256);
    sgemm_kernel<<<gg, tb>>>(queries, Wq, pQ, 1);
    sgemm_kernel<<<gg, tb>>>(keys,    Wk, pK, 1);
    sgemm_kernel<<<gg, tb>>>(values,  Wv, pV, 1);

    dim3 ga(16, 32);
    attn_kernel<<<ga, tb, ATTN_SMEM>>>(rel);

    sgemm_kernel<<<gg, tb>>>(pC, Wo, out, 0);
}

// round 5
// speedup vs baseline: 1.2493x; 1.2493x over previous
#include <cuda_runtime.h>
#include <cuda_bf16.h>
#include <cstdint>

#define S_LEN 1024
#define DHDIM 64
#define NHEADS 8
#define NBATCH 4
#define BHN (NBATCH * NHEADS)
#define ATTN_SMEM (53696 * 4)
#define LDA 40   // padded smem stride (bf16 units) = 80B

// ---------------- scratch ----------------
__device__ float g_Q[BHN * S_LEN * DHDIM];
__device__ float g_K[BHN * S_LEN * DHDIM];
__device__ float g_V[BHN * S_LEN * DHDIM];
__device__ float g_CTX[NBATCH * S_LEN * (NHEADS * DHDIM)];
__device__ __nv_bfloat16 g_Ahi[4096 * 512];
__device__ __nv_bfloat16 g_Alo[4096 * 512];
__device__ __nv_bfloat16 g_Whi[4 * 512 * 512];
__device__ __nv_bfloat16 g_Wlo[4 * 512 * 512];

// ---------------- helpers ----------------
__device__ __forceinline__ uint32_t smaddr(const void* p) {
    return (uint32_t)__cvta_generic_to_shared(p);
}
#define CP16(dst, src) \
    asm volatile("cp.async.cg.shared.global [%0], [%1], 16;" :: "r"(dst), "l"(src))

__device__ __forceinline__ void ldm_x4(uint32_t* r, uint32_t a) {
    asm volatile("ldmatrix.sync.aligned.m8n8.x4.shared.b16 {%0,%1,%2,%3}, [%4];"
                 : "=r"(r[0]), "=r"(r[1]), "=r"(r[2]), "=r"(r[3]) : "r"(a));
}
__device__ __forceinline__ void mma16816(float* c, const uint32_t* a, const uint32_t* b) {
    asm volatile("mma.sync.aligned.m16n8k16.row.col.f32.bf16.bf16.f32 "
                 "{%0,%1,%2,%3}, {%4,%5,%6,%7}, {%8,%9}, {%0,%1,%2,%3};"
                 : "+f"(c[0]), "+f"(c[1]), "+f"(c[2]), "+f"(c[3])
                 : "r"(a[0]), "r"(a[1]), "r"(a[2]), "r"(a[3]), "r"(b[0]), "r"(b[1]));
}

// ---------------- convert kernels ----------------
__global__ void conv_act(const float* __restrict__ x, __nv_bfloat16* __restrict__ hi,
                         __nv_bfloat16* __restrict__ lo, int n4) {
    int i = blockIdx.x * blockDim.x + threadIdx.x;
    if (i >= n4) return;
    float4 v = ((const float4*)x)[i];
    __nv_bfloat16 h0 = __float2bfloat16(v.x), h1 = __float2bfloat16(v.y);
    __nv_bfloat16 h2 = __float2bfloat16(v.z), h3 = __float2bfloat16(v.w);
    __nv_bfloat162* H = (__nv_bfloat162*)hi;
    __nv_bfloat162* L = (__nv_bfloat162*)lo;
    H[2 * i]     = __nv_bfloat162(h0, h1);
    H[2 * i + 1] = __nv_bfloat162(h2, h3);
    L[2 * i]     = __nv_bfloat162(__float2bfloat16(v.x - __bfloat162float(h0)),
                                  __float2bfloat16(v.y - __bfloat162float(h1)));
    L[2 * i + 1] = __nv_bfloat162(__float2bfloat16(v.z - __bfloat162float(h2)),
                                  __float2bfloat16(v.w - __bfloat162float(h3)));
}

// transpose W[k][n] -> out[w][n][k] hi/lo
__global__ void conv_wt(const float* __restrict__ W0, const float* __restrict__ W1,
                        const float* __restrict__ W2, const float* __restrict__ W3,
                        __nv_bfloat16* __restrict__ hi, __nv_bfloat16* __restrict__ lo) {
    __shared__ float t[32][33];
    int w = blockIdx.z;
    const float* W = (w == 0) ? W0 : (w == 1) ? W1 : (w == 2) ? W2 : W3;
    int bx = blockIdx.x, by = blockIdx.y, tx = threadIdx.x, ty = threadIdx.y;
#pragma unroll
    for (int j = 0; j < 32; j += 8)
        t[ty + j][tx] = W[(size_t)(by * 32 + ty + j) * 512 + bx * 32 + tx];
    __syncthreads();
    size_t base = (size_t)w * 512 * 512;
#pragma unroll
    for (int j = 0; j < 32; j += 8) {
        float v = t[tx][ty + j];
        __nv_bfloat16 h = __float2bfloat16(v);
        size_t o = base + (size_t)(bx * 32 + ty + j) * 512 + by * 32 + tx;
        hi[o] = h;
        lo[o] = __float2bfloat16(v - __bfloat162float(h));
    }
}

// ---------------- mma.sync bf16x3 GEMM: C[4096,512] = A @ W  (B = W^T [N][K]) ----------------
// BM=BN=64, BK=32, 128 threads (2x2 warps, 32x32 warp tile), 2-stage cp.async.
__global__ __launch_bounds__(128) void gemm_mma(
    const __nv_bfloat16* __restrict__ Ah, const __nv_bfloat16* __restrict__ Al,
    const __nv_bfloat16* __restrict__ Bh, const __nv_bfloat16* __restrict__ Bl,
    float* __restrict__ C, int split)
{
    __shared__ __nv_bfloat16 sA[2][2][64 * LDA];   // [stage][hi/lo]
    __shared__ __nv_bfloat16 sB[2][2][64 * LDA];
    const int tid = threadIdx.x;
    const int wid = tid >> 5, lane = tid & 31;
    const int m_blk = blockIdx.y * 64, n_blk = blockIdx.x * 64;
    const int wm = (wid >> 1) * 32, wn = (wid & 1) * 32;

    float acc[2][4][4] = {};

    auto load_stage = [&](int stg, int k0) {
        int st = stg & 1;
        int r1 = tid >> 2, sg = tid & 3;
#pragma unroll
        for (int i = 0; i < 2; i++) {
            int r = r1 + i * 32;
            uint32_t off = (uint32_t)(r * LDA + sg * 8) * 2;
            size_t gA = (size_t)(m_blk + r) * 512 + k0 + sg * 8;
            size_t gB = (size_t)(n_blk + r) * 512 + k0 + sg * 8;
            CP16(smaddr(&sA[st][0][0]) + off, Ah + gA);
            CP16(smaddr(&sA[st][1][0]) + off, Al + gA);
            CP16(smaddr(&sB[st][0][0]) + off, Bh + gB);
            CP16(smaddr(&sB[st][1][0]) + off, Bl + gB);
        }
    };

    load_stage(0, 0);
    asm volatile("cp.async.commit_group;");

    for (int s = 0; s < 16; s++) {
        if (s < 15) {
            load_stage(s + 1, (s + 1) * 32);
            asm volatile("cp.async.commit_group;");
            asm volatile("cp.async.wait_group 1;");
        } else {
            asm volatile("cp.async.wait_group 0;");
        }
        __syncthreads();
        int st = s & 1;
#pragma unroll
        for (int kk = 0; kk < 2; kk++) {
            uint32_t ah[2][4], al[2][4], bhf[2][4], blf[2][4];
#pragma unroll
            for (int im = 0; im < 2; im++) {
                int r = wm + im * 16 + (lane & 15);
                int cc = ((lane >> 4) << 3) + kk * 16;
                ldm_x4(ah[im], smaddr(&sA[st][0][r * LDA + cc]));
                ldm_x4(al[im], smaddr(&sA[st][1][r * LDA + cc]));
            }
#pragma unroll
            for (int bt = 0; bt < 2; bt++) {
                int r = wn + bt * 16 + ((lane >> 4) << 3) + (lane & 7);
                int cc = (((lane >> 3) & 1) << 3) + kk * 16;
                ldm_x4(bhf[bt], smaddr(&sB[st][0][r * LDA + cc]));
                ldm_x4(blf[bt], smaddr(&sB[st][1][r * LDA + cc]));
            }
#pragma unroll
            for (int im = 0; im < 2; im++)
#pragma unroll
                for (int in = 0; in < 4; in++) {
                    uint32_t bh2[2] = { bhf[in >> 1][(in & 1) * 2], bhf[in >> 1][(in & 1) * 2 + 1] };
                    uint32_t bl2[2] = { blf[in >> 1][(in & 1) * 2], blf[in >> 1][(in & 1) * 2 + 1] };
                    mma16816(acc[im][in], ah[im], bh2);
                    mma16816(acc[im][in], ah[im], bl2);
                    mma16816(acc[im][in], al[im], bh2);
                }
        }
        __syncthreads();
    }

    // epilogue
#pragma unroll
    for (int im = 0; im < 2; im++)
#pragma unroll
        for (int in = 0; in < 4; in++) {
            int mo = m_blk + wm + im * 16 + (lane >> 2);
            int nn = n_blk + wn + in * 8 + ((lane & 3) << 1);
            if (split) {
                int b = mo >> 10, h = nn >> 6, dh = nn & 63;
                size_t rowbase = (size_t)(b * 8 + h) * 1024;
                *(float2*)&C[(rowbase + (mo & 1023)) * 64 + dh] =
                    make_float2(acc[im][in][0], acc[im][in][1]);
                *(float2*)&C[(rowbase + ((mo + 8) & 1023)) * 64 + dh] =
                    make_float2(acc[im][in][2], acc[im][in][3]);
            } else {
                *(float2*)&C[(size_t)mo * 512 + nn] =
                    make_float2(acc[im][in][0], acc[im][in][1]);
                *(float2*)&C[(size_t)(mo + 8) * 512 + nn] =
                    make_float2(acc[im][in][2], acc[im][in][3]);
            }
        }
}

// ---------------- fused causal attention (unchanged from R3 passing version) ----------------
__global__ __launch_bounds__(256, 1) void attn_kernel(const float* __restrict__ rel)
{
    extern __shared__ float smf[];
    float* q_s   = smf;
    float* k_s   = smf + 4096;
    float* v_s   = smf + 12288;
    float* rel_s = smf + 20480;
    float* qe_s  = smf + 32768;
    float* s_t   = smf + 45056;
    float* m_s   = smf + 53504;
    float* ls_s  = smf + 53568;
    float* al_s  = smf + 53632;

    const int tid = threadIdx.x;
    const int qi = blockIdx.x;
    const int bh = blockIdx.y;
    const int h  = bh & 7;
    const int i0 = qi * 64;
    const float* Qp = g_Q + (size_t)bh * (S_LEN * DHDIM);
    const float* Kp = g_K + (size_t)bh * (S_LEN * DHDIM);
    const float* Vp = g_V + (size_t)bh * (S_LEN * DHDIM);
    const float* Rp = rel + (size_t)h * (DHDIM * S_LEN);

#pragma unroll
    for (int it = 0; it < 4; it++) {
        int lin = tid + it * 256, row = lin >> 4, d4 = (lin & 15) << 2;
        float4 v = *(const float4*)(Qp + (size_t)(i0 + row) * DHDIM + d4);
        q_s[(d4+0)*64+row] = v.x; q_s[(d4+1)*64+row] = v.y;
        q_s[(d4+2)*64+row] = v.z; q_s[(d4+3)*64+row] = v.w;
    }
    if (tid < 64) { m_s[tid] = -3.0e38f; ls_s[tid] = 0.f; }

    const int tr = tid >> 5;
    const int tc = tid & 31;
    float acc_o[8][2];
#pragma unroll
    for (int r = 0; r < 8; r++) { acc_o[r][0] = 0.f; acc_o[r][1] = 0.f; }

    const int ntiles = (i0 + 63) / 128 + 1;
    for (int jt = 0; jt < ntiles; jt++) {
        const int j0 = jt * 128;
        const int lmin = 960 - i0 + j0;
        __syncthreads();
#pragma unroll
        for (int it = 0; it < 8; it++) {
            int lin = tid + it * 256, t = lin >> 4, d4 = (lin & 15) << 2;
            float4 v = *(const float4*)(Kp + (size_t)(j0 + t) * DHDIM + d4);
            k_s[(d4+0)*128+t] = v.x; k_s[(d4+1)*128+t] = v.y;
            k_s[(d4+2)*128+t] = v.z; k_s[(d4+3)*128+t] = v.w;
        }
#pragma unroll
        for (int it = 0; it < 8; it++) {
            int lin = tid + it * 256, t = lin >> 4, d4 = (lin & 15) << 2;
            *(float4*)(v_s + t * 64 + d4) = *(const float4*)(Vp + (size_t)(j0 + t) * DHDIM + d4);
        }
#pragma unroll
        for (int it = 0; it < 12; it++) {
            int lin = tid + it * 256;
            int d = lin / 48, x = (lin % 48) << 2, l = lmin + x;
            float4 v;
            if (l + 3 <= 1023) v = *(const float4*)(Rp + (size_t)d * S_LEN + l);
            else {
                v.x = (l   <= 1023) ? Rp[(size_t)d*S_LEN + l  ] : 0.f;
                v.y = (l+1 <= 1023) ? Rp[(size_t)d*S_LEN + l+1] : 0.f;
                v.z = (l+2 <= 1023) ? Rp[(size_t)d*S_LEN + l+2] : 0.f;
                v.w = 0.f;
            }
            *(float4*)(rel_s + d * 192 + x) = v;
        }
        __syncthreads();

        {
            float a2[8][6];
#pragma unroll
            for (int r = 0; r < 8; r++)
#pragma unroll
                for (int c = 0; c < 6; c++) a2[r][c] = 0.f;
            for (int d = 0; d < 64; d++) {
                float qf[8], rf[6];
                *(float4*)(qf)     = *(float4*)(q_s + d * 64 + tr * 8);
                *(float4*)(qf + 4) = *(float4*)(q_s + d * 64 + tr * 8 + 4);
                *(float2*)(rf)     = *(float2*)(rel_s + d * 192 + tc * 6);
                *(float2*)(rf + 2) = *(float2*)(rel_s + d * 192 + tc * 6 + 2);
                *(float2*)(rf + 4) = *(float2*)(rel_s + d * 192 + tc * 6 + 4);
#pragma unroll
                for (int r = 0; r < 8; r++)
#pragma unroll
                    for (int c = 0; c < 6; c++) a2[r][c] += qf[r] * rf[c];
            }
#pragma unroll
            for (int r = 0; r < 8; r++)
#pragma unroll
                for (int c = 0; c < 6; c += 2)
                    *(float2*)(qe_s + (tr*8+r)*192 + tc*6 + c) = make_float2(a2[r][c], a2[r][c+1]);
        }

        float acc[8][4];
#pragma unroll
        for (int r = 0; r < 8; r++)
#pragma unroll
            for (int c = 0; c < 4; c++) acc[r][c] = 0.f;
        for (int d = 0; d < 64; d++) {
            float qf[8], kf[4];
            *(float4*)(qf)     = *(float4*)(q_s + d * 64 + tr * 8);
            *(float4*)(qf + 4) = *(float4*)(q_s + d * 64 + tr * 8 + 4);
            *(float4*)(kf)     = *(float4*)(k_s + d * 128 + tc * 4);
#pragma unroll
            for (int r = 0; r < 8; r++)
#pragma unroll
                for (int c = 0; c < 4; c++) acc[r][c] += qf[r] * kf[c];
        }
        __syncthreads();

#pragma unroll
        for (int r = 0; r < 8; r++) {
            int ii = tr * 8 + r, i = i0 + ii;
#pragma unroll
            for (int c = 0; c < 4; c++) {
                int tt = tc * 4 + c, t = j0 + tt;
                float qe = qe_s[ii * 192 + (63 - ii + tt)];
                s_t[ii * 132 + tt] = (acc[r][c] + qe + ((t > i) ? -1e9f : 0.f)) * 0.125f;
            }
        }
        __syncthreads();

        {
            int row = tid >> 2, qq = tid & 3;
            float mloc = -3.0e38f;
#pragma unroll
            for (int cc = 0; cc < 32; cc++)
                mloc = fmaxf(mloc, s_t[row * 132 + qq + (cc << 2)]);
            mloc = fmaxf(mloc, __shfl_xor_sync(0xffffffffu, mloc, 1));
            mloc = fmaxf(mloc, __shfl_xor_sync(0xffffffffu, mloc, 2));
            float mold = m_s[row];
            float mnew = fmaxf(mold, mloc);
            float suml = 0.f;
#pragma unroll
            for (int cc = 0; cc < 32; cc++) {
                int idx = row * 132 + qq + (cc << 2);
                float p = __expf(s_t[idx] - mnew);
                s_t[idx] = p;
                suml += p;
            }
            suml += __shfl_xor_sync(0xffffffffu, suml, 1);
            suml += __shfl_xor_sync(0xffffffffu, suml, 2);
            if (qq == 0) {
                float alpha = __expf(mold - mnew);
                al_s[row] = alpha;
                ls_s[row] = ls_s[row] * alpha + suml;
                m_s[row] = mnew;
            }
        }
        __syncthreads();

        {
#pragma unroll
            for (int r = 0; r < 8; r++) {
                float a = al_s[tr * 8 + r];
                acc_o[r][0] *= a; acc_o[r][1] *= a;
            }
            for (int t4 = 0; t4 < 32; t4++) {
                float p4[8][4];
#pragma unroll
                for (int r = 0; r < 8; r++)
                    *(float4*)(p4[r]) = *(float4*)(s_t + (tr*8+r)*132 + (t4 << 2));
#pragma unroll
                for (int u = 0; u < 4; u++) {
                    float2 vv = *(float2*)(v_s + ((t4 << 2) + u) * 64 + tc * 2);
#pragma unroll
                    for (int r = 0; r < 8; r++) {
                        acc_o[r][0] += p4[r][u] * vv.x;
                        acc_o[r][1] += p4[r][u] * vv.y;
                    }
                }
            }
        }
    }

    __syncthreads();
    int b = bh >> 3;
#pragma unroll
    for (int r = 0; r < 8; r++) {
        int ii = tr * 8 + r;
        float inv = 1.f / ls_s[ii];
        *(float2*)(g_CTX + (size_t)(b * S_LEN + i0 + ii) * 512 + h * 64 + tc * 2) =
            make_float2(acc_o[r][0] * inv, acc_o[r][1] * inv);
    }
}

// ---------------- host ----------------
extern "C" void kernel_launch(void* const* d_in, const int* in_sizes, int n_in,
                              void* d_out, int out_size)
{
    const float* queries = (const float*)d_in[0];
    const float* keys    = (const float*)d_in[1];
    const float* values  = (const float*)d_in[2];
    const float* Wq = (const float*)d_in[4];
    const float* Wk = (const float*)d_in[5];
    const float* Wv = (const float*)d_in[6];
    const float* Wo = (const float*)d_in[7];
    const float* rel = (const float*)d_in[8];
    float* out = (float*)d_out;

    float *pQ, *pK, *pV, *pC;
    __nv_bfloat16 *pAh, *pAl, *pWh, *pWl;
    cudaGetSymbolAddress((void**)&pQ, g_Q);
    cudaGetSymbolAddress((void**)&pK, g_K);
    cudaGetSymbolAddress((void**)&pV, g_V);
    cudaGetSymbolAddress((void**)&pC, g_CTX);
    cudaGetSymbolAddress((void**)&pAh, g_Ahi);
    cudaGetSymbolAddress((void**)&pAl, g_Alo);
    cudaGetSymbolAddress((void**)&pWh, g_Whi);
    cudaGetSymbolAddress((void**)&pWl, g_Wlo);

    cudaFuncSetAttribute(attn_kernel, cudaFuncAttributeMaxDynamicSharedMemorySize, ATTN_SMEM);

    const int N4 = 4096 * 512 / 4;
    dim3 cgrid((N4 + 255) / 256), cblk(256);
    dim3 wgrid(16, 16, 4), wblk(32, 8);
    dim3 ggrid(8, 64), gblk(128);

    conv_wt<<<wgrid, wblk>>>(Wq, Wk, Wv, Wo, pWh, pWl);

    conv_act<<<cgrid, cblk>>>(queries, pAh, pAl, N4);
    gemm_mma<<<ggrid, gblk>>>(pAh, pAl, pWh, pWl, pQ, 1);
    conv_act<<<cgrid, cblk>>>(keys, pAh, pAl, N4);
    gemm_mma<<<ggrid, gblk>>>(pAh, pAl, pWh + 1 * 512 * 512, pWl + 1 * 512 * 512, pK, 1);
    conv_act<<<cgrid, cblk>>>(values, pAh, pAl, N4);
    gemm_mma<<<ggrid, gblk>>>(pAh, pAl, pWh + 2 * 512 * 512, pWl + 2 * 512 * 512, pV, 1);

    dim3 ga(16, 32), tb(256);
    attn_kernel<<<ga, tb, ATTN_SMEM>>>(rel);

    conv_act<<<cgrid, cblk>>>(pC, pAh, pAl, N4);
    gemm_mma<<<ggrid, gblk>>>(pAh, pAl, pWh + 3 * 512 * 512, pWl + 3 * 512 * 512, out, 0);
}

// round 7
// speedup vs baseline: 2.4188x; 1.9361x over previous
#include <cuda_runtime.h>
#include <cuda_bf16.h>
#include <cstdint>

#define S_LEN 1024
#define DHDIM 64
#define NHEADS 8
#define NBATCH 4
#define BHN (NBATCH * NHEADS)
#define LDA 40   // gemm smem stride (bf16) = 80B

// attn smem byte offsets (strides chosen: stride*2 mod 128 == 16 -> ldmatrix conflict-free)
#define OFF_QH 0
#define OFF_QL 9216
#define OFF_KH 18432
#define OFF_KL 36864
#define OFF_VH 55296
#define OFF_VL 72704
#define OFF_REL 90112
#define OFF_QE 117760
#define OFF_S 143360
#define OFF_PH 177152
#define OFF_PL 194560
#define OFF_STAT 211968
#define ATTN_SMEM 212736

// ---------------- scratch ----------------
__device__ __nv_bfloat16 g_Ahi[4096 * 512];
__device__ __nv_bfloat16 g_Alo[4096 * 512];
__device__ __nv_bfloat16 g_Whi[4 * 512 * 512];
__device__ __nv_bfloat16 g_Wlo[4 * 512 * 512];
__device__ __nv_bfloat16 g_Qh[BHN * S_LEN * DHDIM];
__device__ __nv_bfloat16 g_Ql[BHN * S_LEN * DHDIM];
__device__ __nv_bfloat16 g_Kh[BHN * S_LEN * DHDIM];
__device__ __nv_bfloat16 g_Kl[BHN * S_LEN * DHDIM];
__device__ __nv_bfloat16 g_Vth[BHN * DHDIM * S_LEN];   // [bh][d][t]
__device__ __nv_bfloat16 g_Vtl[BHN * DHDIM * S_LEN];
__device__ __nv_bfloat16 g_relT[NHEADS * S_LEN * DHDIM]; // [h][l][d]

// ---------------- helpers ----------------
__device__ __forceinline__ uint32_t smaddr(const void* p) {
    return (uint32_t)__cvta_generic_to_shared(p);
}
#define CP16(dst, src) \
    asm volatile("cp.async.cg.shared.global [%0], [%1], 16;" :: "r"(dst), "l"(src))

__device__ __forceinline__ void ldm_x4(uint32_t* r, uint32_t a) {
    asm volatile("ldmatrix.sync.aligned.m8n8.x4.shared.b16 {%0,%1,%2,%3}, [%4];"
                 : "=r"(r[0]), "=r"(r[1]), "=r"(r[2]), "=r"(r[3]) : "r"(a));
}
__device__ __forceinline__ void mma16816(float* c, const uint32_t* a, const uint32_t* b) {
    asm volatile("mma.sync.aligned.m16n8k16.row.col.f32.bf16.bf16.f32 "
                 "{%0,%1,%2,%3}, {%4,%5,%6,%7}, {%8,%9}, {%0,%1,%2,%3};"
                 : "+f"(c[0]), "+f"(c[1]), "+f"(c[2]), "+f"(c[3])
                 : "r"(a[0]), "r"(a[1]), "r"(a[2]), "r"(a[3]), "r"(b[0]), "r"(b[1]));
}
__device__ __forceinline__ void split2(float v0, float v1,
                                       __nv_bfloat162& h2, __nv_bfloat162& l2) {
    __nv_bfloat16 h0 = __float2bfloat16(v0), h1 = __float2bfloat16(v1);
    h2 = __nv_bfloat162(h0, h1);
    l2 = __nv_bfloat162(__float2bfloat16(v0 - __bfloat162float(h0)),
                        __float2bfloat16(v1 - __bfloat162float(h1)));
}

// ---------------- convert kernels ----------------
__global__ void conv_act(const float* __restrict__ x, __nv_bfloat16* __restrict__ hi,
                         __nv_bfloat16* __restrict__ lo, int n4) {
    int i = blockIdx.x * blockDim.x + threadIdx.x;
    if (i >= n4) return;
    float4 v = ((const float4*)x)[i];
    __nv_bfloat162 h2a, l2a, h2b, l2b;
    split2(v.x, v.y, h2a, l2a);
    split2(v.z, v.w, h2b, l2b);
    ((__nv_bfloat162*)hi)[2 * i] = h2a; ((__nv_bfloat162*)hi)[2 * i + 1] = h2b;
    ((__nv_bfloat162*)lo)[2 * i] = l2a; ((__nv_bfloat162*)lo)[2 * i + 1] = l2b;
}

__global__ void conv_wt(const float* __restrict__ W0, const float* __restrict__ W1,
                        const float* __restrict__ W2, const float* __restrict__ W3,
                        __nv_bfloat16* __restrict__ hi, __nv_bfloat16* __restrict__ lo) {
    __shared__ float t[32][33];
    int w = blockIdx.z;
    const float* W = (w == 0) ? W0 : (w == 1) ? W1 : (w == 2) ? W2 : W3;
    int bx = blockIdx.x, by = blockIdx.y, tx = threadIdx.x, ty = threadIdx.y;
#pragma unroll
    for (int j = 0; j < 32; j += 8)
        t[ty + j][tx] = W[(size_t)(by * 32 + ty + j) * 512 + bx * 32 + tx];
    __syncthreads();
    size_t base = (size_t)w * 512 * 512;
#pragma unroll
    for (int j = 0; j < 32; j += 8) {
        float v = t[tx][ty + j];
        __nv_bfloat16 h = __float2bfloat16(v);
        size_t o = base + (size_t)(bx * 32 + ty + j) * 512 + by * 32 + tx;
        hi[o] = h;
        lo[o] = __float2bfloat16(v - __bfloat162float(h));
    }
}

// rel[h][d][l] fp32 -> relT[h][l][d] bf16 (hi only)
__global__ void conv_rel(const float* __restrict__ rel, __nv_bfloat16* __restrict__ relT) {
    __shared__ float t[32][33];
    int hh = blockIdx.z, d0 = blockIdx.y * 32, l0 = blockIdx.x * 32;
    int tx = threadIdx.x, ty = threadIdx.y;
#pragma unroll
    for (int j = 0; j < 32; j += 8)
        t[ty + j][tx] = rel[(size_t)(hh * 64 + d0 + ty + j) * 1024 + l0 + tx];
    __syncthreads();
#pragma unroll
    for (int j = 0; j < 32; j += 8)
        relT[(size_t)(hh * 1024 + l0 + ty + j) * 64 + d0 + tx] = __float2bfloat16(t[tx][ty + j]);
}

// ---------------- mma.sync bf16x3 GEMM ----------------
// mode 0: C fp32 [m][512]. mode 1: Chi/Clo bf16 [b,h][s][dh]. mode 2: Chi/Clo bf16 [b,h][dh][s].
__global__ __launch_bounds__(128) void gemm_mma(
    const __nv_bfloat16* __restrict__ Ah, const __nv_bfloat16* __restrict__ Al,
    const __nv_bfloat16* __restrict__ Bh, const __nv_bfloat16* __restrict__ Bl,
    float* __restrict__ C, __nv_bfloat16* __restrict__ Chi, __nv_bfloat16* __restrict__ Clo,
    int mode)
{
    __shared__ __nv_bfloat16 sA[2][2][64 * LDA];
    __shared__ __nv_bfloat16 sB[2][2][64 * LDA];
    const int tid = threadIdx.x;
    const int wid = tid >> 5, lane = tid & 31;
    const int m_blk = blockIdx.y * 64, n_blk = blockIdx.x * 64;
    const int wm = (wid >> 1) * 32, wn = (wid & 1) * 32;

    float acc[2][4][4] = {};

    auto load_stage = [&](int stg, int k0) {
        int st = stg & 1;
        int r1 = tid >> 2, sg = tid & 3;
#pragma unroll
        for (int i = 0; i < 2; i++) {
            int r = r1 + i * 32;
            uint32_t off = (uint32_t)(r * LDA + sg * 8) * 2;
            size_t gA = (size_t)(m_blk + r) * 512 + k0 + sg * 8;
            size_t gB = (size_t)(n_blk + r) * 512 + k0 + sg * 8;
            CP16(smaddr(&sA[st][0][0]) + off, Ah + gA);
            CP16(smaddr(&sA[st][1][0]) + off, Al + gA);
            CP16(smaddr(&sB[st][0][0]) + off, Bh + gB);
            CP16(smaddr(&sB[st][1][0]) + off, Bl + gB);
        }
    };

    load_stage(0, 0);
    asm volatile("cp.async.commit_group;");

    for (int s = 0; s < 16; s++) {
        if (s < 15) {
            load_stage(s + 1, (s + 1) * 32);
            asm volatile("cp.async.commit_group;");
            asm volatile("cp.async.wait_group 1;");
        } else {
            asm volatile("cp.async.wait_group 0;");
        }
        __syncthreads();
        int st = s & 1;
#pragma unroll
        for (int kk = 0; kk < 2; kk++) {
            uint32_t ah[2][4], al[2][4], bhf[2][4], blf[2][4];
#pragma unroll
            for (int im = 0; im < 2; im++) {
                int r = wm + im * 16 + (lane & 15);
                int cc = ((lane >> 4) << 3) + kk * 16;
                ldm_x4(ah[im], smaddr(&sA[st][0][r * LDA + cc]));
                ldm_x4(al[im], smaddr(&sA[st][1][r * LDA + cc]));
            }
#pragma unroll
            for (int bt = 0; bt < 2; bt++) {
                int r = wn + bt * 16 + ((lane >> 4) << 3) + (lane & 7);
                int cc = (((lane >> 3) & 1) << 3) + kk * 16;
                ldm_x4(bhf[bt], smaddr(&sB[st][0][r * LDA + cc]));
                ldm_x4(blf[bt], smaddr(&sB[st][1][r * LDA + cc]));
            }
#pragma unroll
            for (int im = 0; im < 2; im++)
#pragma unroll
                for (int in = 0; in < 4; in++) {
                    uint32_t bh2[2] = { bhf[in >> 1][(in & 1) * 2], bhf[in >> 1][(in & 1) * 2 + 1] };
                    uint32_t bl2[2] = { blf[in >> 1][(in & 1) * 2], blf[in >> 1][(in & 1) * 2 + 1] };
                    mma16816(acc[im][in], ah[im], bh2);
                    mma16816(acc[im][in], ah[im], bl2);
                    mma16816(acc[im][in], al[im], bh2);
                }
        }
        __syncthreads();
    }

#pragma unroll
    for (int im = 0; im < 2; im++)
#pragma unroll
        for (int in = 0; in < 4; in++) {
            int mo = m_blk + wm + im * 16 + (lane >> 2);
            int nn = n_blk + wn + in * 8 + ((lane & 3) << 1);
            float c0 = acc[im][in][0], c1 = acc[im][in][1];
            float c2 = acc[im][in][2], c3 = acc[im][in][3];
            if (mode == 0) {
                *(float2*)&C[(size_t)mo * 512 + nn] = make_float2(c0, c1);
                *(float2*)&C[(size_t)(mo + 8) * 512 + nn] = make_float2(c2, c3);
            } else {
                int b = mo >> 10, ss = mo & 1023, hh = nn >> 6, dh = nn & 63;
                __nv_bfloat162 h2, l2;
                if (mode == 1) {
                    size_t o = ((size_t)(b * 8 + hh) * 1024 + ss) * 64 + dh;
                    split2(c0, c1, h2, l2);
                    *(__nv_bfloat162*)&Chi[o] = h2; *(__nv_bfloat162*)&Clo[o] = l2;
                    split2(c2, c3, h2, l2);
                    *(__nv_bfloat162*)&Chi[o + 8 * 64] = h2; *(__nv_bfloat162*)&Clo[o + 8 * 64] = l2;
                } else {
                    size_t o = ((size_t)(b * 8 + hh) * 64 + dh) * 1024 + ss;
                    __nv_bfloat16 h;
                    h = __float2bfloat16(c0); Chi[o] = h;
                    Clo[o] = __float2bfloat16(c0 - __bfloat162float(h));
                    h = __float2bfloat16(c1); Chi[o + 1024] = h;
                    Clo[o + 1024] = __float2bfloat16(c1 - __bfloat162float(h));
                    h = __float2bfloat16(c2); Chi[o + 8] = h;
                    Clo[o + 8] = __float2bfloat16(c2 - __bfloat162float(h));
                    h = __float2bfloat16(c3); Chi[o + 1024 + 8] = h;
                    Clo[o + 1024 + 8] = __float2bfloat16(c3 - __bfloat162float(h));
                }
            }
        }
}

// ---------------- mma.sync fused causal attention ----------------
// BM=64 query rows, BN=128 keys/tile, 256 threads (8 warps).
__global__ __launch_bounds__(256, 1) void attn_kernel()
{
    extern __shared__ __align__(16) char smc[];
    __nv_bfloat16* sQh  = (__nv_bfloat16*)(smc + OFF_QH);   // [64][72]
    __nv_bfloat16* sQl  = (__nv_bfloat16*)(smc + OFF_QL);
    __nv_bfloat16* sKh  = (__nv_bfloat16*)(smc + OFF_KH);   // [128][72]
    __nv_bfloat16* sKl  = (__nv_bfloat16*)(smc + OFF_KL);
    __nv_bfloat16* sVh  = (__nv_bfloat16*)(smc + OFF_VH);   // [64 d][136 t]
    __nv_bfloat16* sVl  = (__nv_bfloat16*)(smc + OFF_VL);
    __nv_bfloat16* sRel = (__nv_bfloat16*)(smc + OFF_REL);  // [192 x][72 d]
    __nv_bfloat16* sQe  = (__nv_bfloat16*)(smc + OFF_QE);   // [64][200]
    float* s_t  = (float*)(smc + OFF_S);                    // [64][132]
    __nv_bfloat16* sPh  = (__nv_bfloat16*)(smc + OFF_PH);   // [64][136]
    __nv_bfloat16* sPl  = (__nv_bfloat16*)(smc + OFF_PL);
    float* m_s  = (float*)(smc + OFF_STAT);
    float* ls_s = (float*)(smc + OFF_STAT + 256);
    float* al_s = (float*)(smc + OFF_STAT + 512);

    const int tid = threadIdx.x;
    const int wid = tid >> 5, lane = tid & 31;
    const int qi = blockIdx.x, bh = blockIdx.y;
    const int h = bh & 7, b = bh >> 3;
    const int i0 = qi * 64;
    const int wm = (wid >> 2) * 32;          // 0 / 32

    // load Q tile hi/lo
#pragma unroll
    for (int it = 0; it < 2; it++) {
        int idx = tid + it * 256, r = idx >> 3, sg = idx & 7;
        size_t g = ((size_t)bh * 1024 + i0 + r) * 64 + sg * 8;
        *(uint4*)&sQh[r * 72 + sg * 8] = *(const uint4*)&g_Qh[g];
        *(uint4*)&sQl[r * 72 + sg * 8] = *(const uint4*)&g_Ql[g];
    }
    if (tid < 64) { m_s[tid] = -3.0e38f; ls_s[tid] = 0.f; }

    float acc_o[2][2][4] = {};
    const int ntiles = (i0 + 63) / 128 + 1;

    for (int jt = 0; jt < ntiles; jt++) {
        const int j0 = jt * 128;
        const int lmin = 960 - i0 + j0;
        __syncthreads();
        // K tile hi/lo [128][72]
#pragma unroll
        for (int it = 0; it < 4; it++) {
            int idx = tid + it * 256, t = idx >> 3, sg = idx & 7;
            size_t g = ((size_t)bh * 1024 + j0 + t) * 64 + sg * 8;
            *(uint4*)&sKh[t * 72 + sg * 8] = *(const uint4*)&g_Kh[g];
            *(uint4*)&sKl[t * 72 + sg * 8] = *(const uint4*)&g_Kl[g];
        }
        // VT tile hi/lo [64 d][136]
#pragma unroll
        for (int it = 0; it < 4; it++) {
            int idx = tid + it * 256, dd = idx >> 4, sg = idx & 15;
            size_t g = ((size_t)bh * 64 + dd) * 1024 + j0 + sg * 8;
            *(uint4*)&sVh[dd * 136 + sg * 8] = *(const uint4*)&g_Vth[g];
            *(uint4*)&sVl[dd * 136 + sg * 8] = *(const uint4*)&g_Vtl[g];
        }
        // rel band [192 x][72 d], zero beyond l=1023
#pragma unroll
        for (int it = 0; it < 6; it++) {
            int idx = tid + it * 256, x = idx >> 3, sg = idx & 7;
            int l = lmin + x;
            uint4 v = make_uint4(0, 0, 0, 0);
            if (l <= 1023)
                v = *(const uint4*)&g_relT[((size_t)h * 1024 + l) * 64 + sg * 8];
            *(uint4*)&sRel[x * 72 + sg * 8] = v;
        }
        __syncthreads();

        // ---- QE band GEMM (bf16 single): qe[64][192] ----
        {
            const int wne = (wid & 3) * 48;
            float eacc[2][6][4] = {};
#pragma unroll
            for (int kk = 0; kk < 4; kk++) {
                uint32_t aq[2][4], br[3][4];
#pragma unroll
                for (int im = 0; im < 2; im++)
                    ldm_x4(aq[im], smaddr(&sQh[(wm + im * 16 + (lane & 15)) * 72 +
                                               ((lane >> 4) << 3) + kk * 16]));
#pragma unroll
                for (int bt = 0; bt < 3; bt++)
                    ldm_x4(br[bt], smaddr(&sRel[(wne + bt * 16 + ((lane >> 4) << 3) + (lane & 7)) * 72 +
                                                (((lane >> 3) & 1) << 3) + kk * 16]));
#pragma unroll
                for (int im = 0; im < 2; im++)
#pragma unroll
                    for (int in = 0; in < 6; in++) {
                        uint32_t b2[2] = { br[in >> 1][(in & 1) * 2], br[in >> 1][(in & 1) * 2 + 1] };
                        mma16816(eacc[im][in], aq[im], b2);
                    }
            }
#pragma unroll
            for (int im = 0; im < 2; im++)
#pragma unroll
                for (int in = 0; in < 6; in++) {
                    int i = wm + im * 16 + (lane >> 2);
                    int x = wne + in * 8 + ((lane & 3) << 1);
                    *(__nv_bfloat162*)&sQe[i * 200 + x] =
                        __nv_bfloat162(__float2bfloat16(eacc[im][in][0]),
                                       __float2bfloat16(eacc[im][in][1]));
                    *(__nv_bfloat162*)&sQe[(i + 8) * 200 + x] =
                        __nv_bfloat162(__float2bfloat16(eacc[im][in][2]),
                                       __float2bfloat16(eacc[im][in][3]));
                }
        }

        // ---- QK^T (bf16x3) ----
        float acc[2][4][4] = {};
        {
            const int wn = (wid & 3) * 32;
#pragma unroll
            for (int kk = 0; kk < 4; kk++) {
                uint32_t ah[2][4], al[2][4], bhf[2][4], blf[2][4];
#pragma unroll
                for (int im = 0; im < 2; im++) {
                    int r = wm + im * 16 + (lane & 15);
                    int cc = ((lane >> 4) << 3) + kk * 16;
                    ldm_x4(ah[im], smaddr(&sQh[r * 72 + cc]));
                    ldm_x4(al[im], smaddr(&sQl[r * 72 + cc]));
                }
#pragma unroll
                for (int bt = 0; bt < 2; bt++) {
                    int r = wn + bt * 16 + ((lane >> 4) << 3) + (lane & 7);
                    int cc = (((lane >> 3) & 1) << 3) + kk * 16;
                    ldm_x4(bhf[bt], smaddr(&sKh[r * 72 + cc]));
                    ldm_x4(blf[bt], smaddr(&sKl[r * 72 + cc]));
                }
#pragma unroll
                for (int im = 0; im < 2; im++)
#pragma unroll
                    for (int in = 0; in < 4; in++) {
                        uint32_t b2h[2] = { bhf[in >> 1][(in & 1) * 2], bhf[in >> 1][(in & 1) * 2 + 1] };
                        uint32_t b2l[2] = { blf[in >> 1][(in & 1) * 2], blf[in >> 1][(in & 1) * 2 + 1] };
                        mma16816(acc[im][in], ah[im], b2h);
                        mma16816(acc[im][in], ah[im], b2l);
                        mma16816(acc[im][in], al[im], b2h);
                    }
            }
        }
        __syncthreads();   // qe visible

        // ---- scores = (QK + gather(qe) + mask) * scale ----
        {
            const int wn = (wid & 3) * 32;
#pragma unroll
            for (int im = 0; im < 2; im++)
#pragma unroll
                for (int in = 0; in < 4; in++) {
#pragma unroll
                    for (int half = 0; half < 2; half++) {
                        int ii = wm + im * 16 + (lane >> 2) + half * 8;
                        float v0 = acc[im][in][half * 2], v1 = acc[im][in][half * 2 + 1];
                        int tt = wn + in * 8 + ((lane & 3) << 1);
                        float q0 = __bfloat162float(sQe[ii * 200 + (63 - ii + tt)]);
                        float q1 = __bfloat162float(sQe[ii * 200 + (63 - ii + tt + 1)]);
                        int ig = i0 + ii;
                        float m0 = (j0 + tt > ig) ? -1e9f : 0.f;
                        float m1 = (j0 + tt + 1 > ig) ? -1e9f : 0.f;
                        s_t[ii * 132 + tt]     = (v0 + q0 + m0) * 0.125f;
                        s_t[ii * 132 + tt + 1] = (v1 + q1 + m1) * 0.125f;
                    }
                }
        }
        __syncthreads();

        // ---- online softmax (fp32), write P hi/lo ----
        {
            int row = tid >> 2, qq = tid & 3;
            float mloc = -3.0e38f;
#pragma unroll
            for (int cc = 0; cc < 32; cc++)
                mloc = fmaxf(mloc, s_t[row * 132 + qq + (cc << 2)]);
            mloc = fmaxf(mloc, __shfl_xor_sync(0xffffffffu, mloc, 1));
            mloc = fmaxf(mloc, __shfl_xor_sync(0xffffffffu, mloc, 2));
            float mold = m_s[row];
            float mnew = fmaxf(mold, mloc);
            float suml = 0.f;
#pragma unroll
            for (int cc = 0; cc < 32; cc++) {
                int col = qq + (cc << 2);
                float p = __expf(s_t[row * 132 + col] - mnew);
                suml += p;
                __nv_bfloat16 ph = __float2bfloat16(p);
                sPh[row * 136 + col] = ph;
                sPl[row * 136 + col] = __float2bfloat16(p - __bfloat162float(ph));
            }
            suml += __shfl_xor_sync(0xffffffffu, suml, 1);
            suml += __shfl_xor_sync(0xffffffffu, suml, 2);
            if (qq == 0) {
                float alpha = __expf(mold - mnew);
                al_s[row] = alpha;
                ls_s[row] = ls_s[row] * alpha + suml;
                m_s[row] = mnew;
            }
        }
        __syncthreads();

        // ---- O = O*alpha + P @ V  (bf16x3) ----
        {
            const int wnp = (wid & 3) * 16;
#pragma unroll
            for (int im = 0; im < 2; im++) {
                float a0 = al_s[wm + im * 16 + (lane >> 2)];
                float a1 = al_s[wm + im * 16 + (lane >> 2) + 8];
#pragma unroll
                for (int in = 0; in < 2; in++) {
                    acc_o[im][in][0] *= a0; acc_o[im][in][1] *= a0;
                    acc_o[im][in][2] *= a1; acc_o[im][in][3] *= a1;
                }
            }
#pragma unroll
            for (int kk = 0; kk < 8; kk++) {
                uint32_t ph[2][4], pl[2][4], bv[4], bvl[4];
#pragma unroll
                for (int im = 0; im < 2; im++) {
                    int r = wm + im * 16 + (lane & 15);
                    int cc = ((lane >> 4) << 3) + kk * 16;
                    ldm_x4(ph[im], smaddr(&sPh[r * 136 + cc]));
                    ldm_x4(pl[im], smaddr(&sPl[r * 136 + cc]));
                }
                {
                    int r = wnp + ((lane >> 4) << 3) + (lane & 7);
                    int cc = (((lane >> 3) & 1) << 3) + kk * 16;
                    ldm_x4(bv,  smaddr(&sVh[r * 136 + cc]));
                    ldm_x4(bvl, smaddr(&sVl[r * 136 + cc]));
                }
#pragma unroll
                for (int im = 0; im < 2; im++)
#pragma unroll
                    for (int in = 0; in < 2; in++) {
                        uint32_t b2h[2] = { bv[in * 2], bv[in * 2 + 1] };
                        uint32_t b2l[2] = { bvl[in * 2], bvl[in * 2 + 1] };
                        mma16816(acc_o[im][in], ph[im], b2h);
                        mma16816(acc_o[im][in], pl[im], b2h);
                        mma16816(acc_o[im][in], ph[im], b2l);
                    }
            }
        }
    }

    // epilogue: O /= ls, write ctx hi/lo into final-GEMM input buffers
    {
        const int wnp = (wid & 3) * 16;
#pragma unroll
        for (int im = 0; im < 2; im++)
#pragma unroll
            for (int in = 0; in < 2; in++) {
                int i = wm + im * 16 + (lane >> 2);
                int d = wnp + in * 8 + ((lane & 3) << 1);
                float inv0 = 1.f / ls_s[i];
                float inv1 = 1.f / ls_s[i + 8];
                size_t o = (size_t)(b * 1024 + i0 + i) * 512 + h * 64 + d;
                __nv_bfloat162 h2, l2;
                split2(acc_o[im][in][0] * inv0, acc_o[im][in][1] * inv0, h2, l2);
                *(__nv_bfloat162*)&g_Ahi[o] = h2; *(__nv_bfloat162*)&g_Alo[o] = l2;
                split2(acc_o[im][in][2] * inv1, acc_o[im][in][3] * inv1, h2, l2);
                *(__nv_bfloat162*)&g_Ahi[o + 8 * 512] = h2;
                *(__nv_bfloat162*)&g_Alo[o + 8 * 512] = l2;
            }
    }
}

// ---------------- host ----------------
extern "C" void kernel_launch(void* const* d_in, const int* in_sizes, int n_in,
                              void* d_out, int out_size)
{
    const float* queries = (const float*)d_in[0];
    const float* keys    = (const float*)d_in[1];
    const float* values  = (const float*)d_in[2];
    const float* Wq = (const float*)d_in[4];
    const float* Wk = (const float*)d_in[5];
    const float* Wv = (const float*)d_in[6];
    const float* Wo = (const float*)d_in[7];
    const float* rel = (const float*)d_in[8];
    float* out = (float*)d_out;

    __nv_bfloat16 *pAh, *pAl, *pWh, *pWl, *pQh, *pQl, *pKh, *pKl, *pVh, *pVl, *pRT;
    cudaGetSymbolAddress((void**)&pAh, g_Ahi);
    cudaGetSymbolAddress((void**)&pAl, g_Alo);
    cudaGetSymbolAddress((void**)&pWh, g_Whi);
    cudaGetSymbolAddress((void**)&pWl, g_Wlo);
    cudaGetSymbolAddress((void**)&pQh, g_Qh);
    cudaGetSymbolAddress((void**)&pQl, g_Ql);
    cudaGetSymbolAddress((void**)&pKh, g_Kh);
    cudaGetSymbolAddress((void**)&pKl, g_Kl);
    cudaGetSymbolAddress((void**)&pVh, g_Vth);
    cudaGetSymbolAddress((void**)&pVl, g_Vtl);
    cudaGetSymbolAddress((void**)&pRT, g_relT);

    cudaFuncSetAttribute(attn_kernel, cudaFuncAttributeMaxDynamicSharedMemorySize, ATTN_SMEM);

    const int N4 = 4096 * 512 / 4;
    dim3 cgrid((N4 + 255) / 256), cblk(256);
    dim3 wgrid(16, 16, 4), wblk(32, 8);
    dim3 rgrid(32, 2, 8);
    dim3 ggrid(8, 64), gblk(128);

    conv_wt<<<wgrid, wblk>>>(Wq, Wk, Wv, Wo, pWh, pWl);
    conv_rel<<<rgrid, wblk>>>(rel, pRT);

    conv_act<<<cgrid, cblk>>>(queries, pAh, pAl, N4);
    gemm_mma<<<ggrid, gblk>>>(pAh, pAl, pWh, pWl, nullptr, pQh, pQl, 1);
    conv_act<<<cgrid, cblk>>>(keys, pAh, pAl, N4);
    gemm_mma<<<ggrid, gblk>>>(pAh, pAl, pWh + 1 * 512 * 512, pWl + 1 * 512 * 512,
                              nullptr, pKh, pKl, 1);
    conv_act<<<cgrid, cblk>>>(values, pAh, pAl, N4);
    gemm_mma<<<ggrid, gblk>>>(pAh, pAl, pWh + 2 * 512 * 512, pWl + 2 * 512 * 512,
                              nullptr, pVh, pVl, 2);

    dim3 ga(16, 32), tb(256);
    attn_kernel<<<ga, tb, ATTN_SMEM>>>();

    gemm_mma<<<ggrid, gblk>>>(pAh, pAl, pWh + 3 * 512 * 512, pWl + 3 * 512 * 512,
                              out, nullptr, nullptr, 0);
}

// round 9
// speedup vs baseline: 2.5408x; 1.0504x over previous
#include <cuda_runtime.h>
#include <cuda_bf16.h>
#include <cstdint>

#define S_LEN 1024
#define DHDIM 64
#define NHEADS 8
#define NBATCH 4
#define BHN (NBATCH * NHEADS)
#define LDA 40   // gemm smem stride (bf16) = 80B

// attn smem byte offsets
#define OFF_QH 0
#define OFF_QL 9216
#define OFF_KH 18432
#define OFF_KL 36864
#define OFF_VH 55296
#define OFF_VL 72704
#define OFF_REL 90112
#define OFF_QE 117760
#define OFF_S 143360
#define OFF_PH 177152
#define OFF_PL 194560
#define OFF_STAT 211968
#define ATTN_SMEM 212736

// ---------------- scratch ----------------
__device__ __nv_bfloat16 g_Ahi[4096 * 512];     // ctx hi (attn out -> final gemm)
__device__ __nv_bfloat16 g_Alo[4096 * 512];
__device__ __nv_bfloat16 g_A0h[4096 * 512];     // queries split
__device__ __nv_bfloat16 g_A0l[4096 * 512];
__device__ __nv_bfloat16 g_A1h[4096 * 512];     // keys split
__device__ __nv_bfloat16 g_A1l[4096 * 512];
__device__ __nv_bfloat16 g_A2h[4096 * 512];     // values split
__device__ __nv_bfloat16 g_A2l[4096 * 512];
__device__ __nv_bfloat16 g_Whi[4 * 512 * 512];
__device__ __nv_bfloat16 g_Wlo[4 * 512 * 512];
__device__ __nv_bfloat16 g_Qh[BHN * S_LEN * DHDIM];
__device__ __nv_bfloat16 g_Ql[BHN * S_LEN * DHDIM];
__device__ __nv_bfloat16 g_Kh[BHN * S_LEN * DHDIM];
__device__ __nv_bfloat16 g_Kl[BHN * S_LEN * DHDIM];
__device__ __nv_bfloat16 g_Vth[BHN * DHDIM * S_LEN];   // [bh][d][t]
__device__ __nv_bfloat16 g_Vtl[BHN * DHDIM * S_LEN];
__device__ __nv_bfloat16 g_relT[NHEADS * S_LEN * DHDIM]; // [h][l][d]

// ---------------- helpers ----------------
__device__ __forceinline__ uint32_t smaddr(const void* p) {
    return (uint32_t)__cvta_generic_to_shared(p);
}
#define CP16(dst, src) \
    asm volatile("cp.async.cg.shared.global [%0], [%1], 16;" :: "r"(dst), "l"(src))

__device__ __forceinline__ void ldm_x4(uint32_t* r, uint32_t a) {
    asm volatile("ldmatrix.sync.aligned.m8n8.x4.shared.b16 {%0,%1,%2,%3}, [%4];"
                 : "=r"(r[0]), "=r"(r[1]), "=r"(r[2]), "=r"(r[3]) : "r"(a));
}
__device__ __forceinline__ void mma16816(float* c, const uint32_t* a, const uint32_t* b) {
    asm volatile("mma.sync.aligned.m16n8k16.row.col.f32.bf16.bf16.f32 "
                 "{%0,%1,%2,%3}, {%4,%5,%6,%7}, {%8,%9}, {%0,%1,%2,%3};"
                 : "+f"(c[0]), "+f"(c[1]), "+f"(c[2]), "+f"(c[3])
                 : "r"(a[0]), "r"(a[1]), "r"(a[2]), "r"(a[3]), "r"(b[0]), "r"(b[1]));
}
__device__ __forceinline__ void split2(float v0, float v1,
                                       __nv_bfloat162& h2, __nv_bfloat162& l2) {
    __nv_bfloat16 h0 = __float2bfloat16(v0), h1 = __float2bfloat16(v1);
    h2 = __nv_bfloat162(h0, h1);
    l2 = __nv_bfloat162(__float2bfloat16(v0 - __bfloat162float(h0)),
                        __float2bfloat16(v1 - __bfloat162float(h1)));
}

// ---------------- convert kernels ----------------
// one launch converts queries/keys/values (blockIdx.y selects)
__global__ void conv_act3(const float* __restrict__ q, const float* __restrict__ k,
                          const float* __restrict__ v, int n4) {
    int i = blockIdx.x * blockDim.x + threadIdx.x;
    if (i >= n4) return;
    int w = blockIdx.y;
    const float* x = (w == 0) ? q : (w == 1) ? k : v;
    __nv_bfloat16* hi = (w == 0) ? g_A0h : (w == 1) ? g_A1h : g_A2h;
    __nv_bfloat16* lo = (w == 0) ? g_A0l : (w == 1) ? g_A1l : g_A2l;
    float4 val = ((const float4*)x)[i];
    __nv_bfloat162 h2a, l2a, h2b, l2b;
    split2(val.x, val.y, h2a, l2a);
    split2(val.z, val.w, h2b, l2b);
    ((__nv_bfloat162*)hi)[2 * i] = h2a; ((__nv_bfloat162*)hi)[2 * i + 1] = h2b;
    ((__nv_bfloat162*)lo)[2 * i] = l2a; ((__nv_bfloat162*)lo)[2 * i + 1] = l2b;
}

// ctx fp32 -> hi/lo (for final gemm input) -- used only by attn epilogue (inline there)

__global__ void conv_wt(const float* __restrict__ W0, const float* __restrict__ W1,
                        const float* __restrict__ W2, const float* __restrict__ W3,
                        __nv_bfloat16* __restrict__ hi, __nv_bfloat16* __restrict__ lo) {
    __shared__ float t[32][33];
    int w = blockIdx.z;
    const float* W = (w == 0) ? W0 : (w == 1) ? W1 : (w == 2) ? W2 : W3;
    int bx = blockIdx.x, by = blockIdx.y, tx = threadIdx.x, ty = threadIdx.y;
#pragma unroll
    for (int j = 0; j < 32; j += 8)
        t[ty + j][tx] = W[(size_t)(by * 32 + ty + j) * 512 + bx * 32 + tx];
    __syncthreads();
    size_t base = (size_t)w * 512 * 512;
#pragma unroll
    for (int j = 0; j < 32; j += 8) {
        float v = t[tx][ty + j];
        __nv_bfloat16 h = __float2bfloat16(v);
        size_t o = base + (size_t)(bx * 32 + ty + j) * 512 + by * 32 + tx;
        hi[o] = h;
        lo[o] = __float2bfloat16(v - __bfloat162float(h));
    }
}

__global__ void conv_rel(const float* __restrict__ rel, __nv_bfloat16* __restrict__ relT) {
    __shared__ float t[32][33];
    int hh = blockIdx.z, d0 = blockIdx.y * 32, l0 = blockIdx.x * 32;
    int tx = threadIdx.x, ty = threadIdx.y;
#pragma unroll
    for (int j = 0; j < 32; j += 8)
        t[ty + j][tx] = rel[(size_t)(hh * 64 + d0 + ty + j) * 1024 + l0 + tx];
    __syncthreads();
#pragma unroll
    for (int j = 0; j < 32; j += 8)
        relT[(size_t)(hh * 1024 + l0 + ty + j) * 64 + d0 + tx] = __float2bfloat16(t[tx][ty + j]);
}

// ---------------- merged QKV projection GEMM (blockIdx.z = which projection) ----------------
// C_z[4096,512] = A_z @ W_z^T; z=0,1 -> head-split hi/lo [b,h][s][dh]; z=2 -> transposed [b,h][dh][s]
__global__ __launch_bounds__(128) void gemm_qkv()
{
    __shared__ __nv_bfloat16 sA[2][2][64 * LDA];
    __shared__ __nv_bfloat16 sB[2][2][64 * LDA];
    const int z = blockIdx.z;
    const __nv_bfloat16* Ah = (z == 0) ? g_A0h : (z == 1) ? g_A1h : g_A2h;
    const __nv_bfloat16* Al = (z == 0) ? g_A0l : (z == 1) ? g_A1l : g_A2l;
    const __nv_bfloat16* Bh = g_Whi + (size_t)z * 512 * 512;
    const __nv_bfloat16* Bl = g_Wlo + (size_t)z * 512 * 512;
    const int tid = threadIdx.x;
    const int wid = tid >> 5, lane = tid & 31;
    const int m_blk = blockIdx.y * 64, n_blk = blockIdx.x * 64;
    const int wm = (wid >> 1) * 32, wn = (wid & 1) * 32;

    float acc[2][4][4] = {};

    auto load_stage = [&](int stg, int k0) {
        int st = stg & 1;
        int r1 = tid >> 2, sg = tid & 3;
#pragma unroll
        for (int i = 0; i < 2; i++) {
            int r = r1 + i * 32;
            uint32_t off = (uint32_t)(r * LDA + sg * 8) * 2;
            size_t gA = (size_t)(m_blk + r) * 512 + k0 + sg * 8;
            size_t gB = (size_t)(n_blk + r) * 512 + k0 + sg * 8;
            CP16(smaddr(&sA[st][0][0]) + off, Ah + gA);
            CP16(smaddr(&sA[st][1][0]) + off, Al + gA);
            CP16(smaddr(&sB[st][0][0]) + off, Bh + gB);
            CP16(smaddr(&sB[st][1][0]) + off, Bl + gB);
        }
    };

    load_stage(0, 0);
    asm volatile("cp.async.commit_group;");

    for (int s = 0; s < 16; s++) {
        if (s < 15) {
            load_stage(s + 1, (s + 1) * 32);
            asm volatile("cp.async.commit_group;");
            asm volatile("cp.async.wait_group 1;");
        } else {
            asm volatile("cp.async.wait_group 0;");
        }
        __syncthreads();
        int st = s & 1;
#pragma unroll
        for (int kk = 0; kk < 2; kk++) {
            uint32_t ah[2][4], al[2][4], bhf[2][4], blf[2][4];
#pragma unroll
            for (int im = 0; im < 2; im++) {
                int r = wm + im * 16 + (lane & 15);
                int cc = ((lane >> 4) << 3) + kk * 16;
                ldm_x4(ah[im], smaddr(&sA[st][0][r * LDA + cc]));
                ldm_x4(al[im], smaddr(&sA[st][1][r * LDA + cc]));
            }
#pragma unroll
            for (int bt = 0; bt < 2; bt++) {
                int r = wn + bt * 16 + ((lane >> 4) << 3) + (lane & 7);
                int cc = (((lane >> 3) & 1) << 3) + kk * 16;
                ldm_x4(bhf[bt], smaddr(&sB[st][0][r * LDA + cc]));
                ldm_x4(blf[bt], smaddr(&sB[st][1][r * LDA + cc]));
            }
#pragma unroll
            for (int im = 0; im < 2; im++)
#pragma unroll
                for (int in = 0; in < 4; in++) {
                    uint32_t bh2[2] = { bhf[in >> 1][(in & 1) * 2], bhf[in >> 1][(in & 1) * 2 + 1] };
                    uint32_t bl2[2] = { blf[in >> 1][(in & 1) * 2], blf[in >> 1][(in & 1) * 2 + 1] };
                    mma16816(acc[im][in], ah[im], bh2);
                    mma16816(acc[im][in], ah[im], bl2);
                    mma16816(acc[im][in], al[im], bh2);
                }
        }
        __syncthreads();
    }

    __nv_bfloat16* Chi = (z == 0) ? g_Qh : (z == 1) ? g_Kh : g_Vth;
    __nv_bfloat16* Clo = (z == 0) ? g_Ql : (z == 1) ? g_Kl : g_Vtl;
#pragma unroll
    for (int im = 0; im < 2; im++)
#pragma unroll
        for (int in = 0; in < 4; in++) {
            int mo = m_blk + wm + im * 16 + (lane >> 2);
            int nn = n_blk + wn + in * 8 + ((lane & 3) << 1);
            float c0 = acc[im][in][0], c1 = acc[im][in][1];
            float c2 = acc[im][in][2], c3 = acc[im][in][3];
            int b = mo >> 10, ss = mo & 1023, hh = nn >> 6, dh = nn & 63;
            if (z < 2) {
                size_t o = ((size_t)(b * 8 + hh) * 1024 + ss) * 64 + dh;
                __nv_bfloat162 h2, l2;
                split2(c0, c1, h2, l2);
                *(__nv_bfloat162*)&Chi[o] = h2; *(__nv_bfloat162*)&Clo[o] = l2;
                split2(c2, c3, h2, l2);
                *(__nv_bfloat162*)&Chi[o + 8 * 64] = h2; *(__nv_bfloat162*)&Clo[o + 8 * 64] = l2;
            } else {
                size_t o = ((size_t)(b * 8 + hh) * 64 + dh) * 1024 + ss;
                __nv_bfloat16 h;
                h = __float2bfloat16(c0); Chi[o] = h;
                Clo[o] = __float2bfloat16(c0 - __bfloat162float(h));
                h = __float2bfloat16(c1); Chi[o + 1024] = h;
                Clo[o + 1024] = __float2bfloat16(c1 - __bfloat162float(h));
                h = __float2bfloat16(c2); Chi[o + 8] = h;
                Clo[o + 8] = __float2bfloat16(c2 - __bfloat162float(h));
                h = __float2bfloat16(c3); Chi[o + 1024 + 8] = h;
                Clo[o + 1024 + 8] = __float2bfloat16(c3 - __bfloat162float(h));
            }
        }
}

// ---------------- output GEMM: out = ctx @ Wo (fp32 out) ----------------
__global__ __launch_bounds__(128) void gemm_out(float* __restrict__ C)
{
    __shared__ __nv_bfloat16 sA[2][2][64 * LDA];
    __shared__ __nv_bfloat16 sB[2][2][64 * LDA];
    const __nv_bfloat16* Ah = g_Ahi;
    const __nv_bfloat16* Al = g_Alo;
    const __nv_bfloat16* Bh = g_Whi + (size_t)3 * 512 * 512;
    const __nv_bfloat16* Bl = g_Wlo + (size_t)3 * 512 * 512;
    const int tid = threadIdx.x;
    const int wid = tid >> 5, lane = tid & 31;
    const int m_blk = blockIdx.y * 64, n_blk = blockIdx.x * 64;
    const int wm = (wid >> 1) * 32, wn = (wid & 1) * 32;

    float acc[2][4][4] = {};

    auto load_stage = [&](int stg, int k0) {
        int st = stg & 1;
        int r1 = tid >> 2, sg = tid & 3;
#pragma unroll
        for (int i = 0; i < 2; i++) {
            int r = r1 + i * 32;
            uint32_t off = (uint32_t)(r * LDA + sg * 8) * 2;
            size_t gA = (size_t)(m_blk + r) * 512 + k0 + sg * 8;
            size_t gB = (size_t)(n_blk + r) * 512 + k0 + sg * 8;
            CP16(smaddr(&sA[st][0][0]) + off, Ah + gA);
            CP16(smaddr(&sA[st][1][0]) + off, Al + gA);
            CP16(smaddr(&sB[st][0][0]) + off, Bh + gB);
            CP16(smaddr(&sB[st][1][0]) + off, Bl + gB);
        }
    };

    load_stage(0, 0);
    asm volatile("cp.async.commit_group;");

    for (int s = 0; s < 16; s++) {
        if (s < 15) {
            load_stage(s + 1, (s + 1) * 32);
            asm volatile("cp.async.commit_group;");
            asm volatile("cp.async.wait_group 1;");
        } else {
            asm volatile("cp.async.wait_group 0;");
        }
        __syncthreads();
        int st = s & 1;
#pragma unroll
        for (int kk = 0; kk < 2; kk++) {
            uint32_t ah[2][4], al[2][4], bhf[2][4], blf[2][4];
#pragma unroll
            for (int im = 0; im < 2; im++) {
                int r = wm + im * 16 + (lane & 15);
                int cc = ((lane >> 4) << 3) + kk * 16;
                ldm_x4(ah[im], smaddr(&sA[st][0][r * LDA + cc]));
                ldm_x4(al[im], smaddr(&sA[st][1][r * LDA + cc]));
            }
#pragma unroll
            for (int bt = 0; bt < 2; bt++) {
                int r = wn + bt * 16 + ((lane >> 4) << 3) + (lane & 7);
                int cc = (((lane >> 3) & 1) << 3) + kk * 16;
                ldm_x4(bhf[bt], smaddr(&sB[st][0][r * LDA + cc]));
                ldm_x4(blf[bt], smaddr(&sB[st][1][r * LDA + cc]));
            }
#pragma unroll
            for (int im = 0; im < 2; im++)
#pragma unroll
                for (int in = 0; in < 4; in++) {
                    uint32_t bh2[2] = { bhf[in >> 1][(in & 1) * 2], bhf[in >> 1][(in & 1) * 2 + 1] };
                    uint32_t bl2[2] = { blf[in >> 1][(in & 1) * 2], blf[in >> 1][(in & 1) * 2 + 1] };
                    mma16816(acc[im][in], ah[im], bh2);
                    mma16816(acc[im][in], ah[im], bl2);
                    mma16816(acc[im][in], al[im], bh2);
                }
        }
        __syncthreads();
    }

#pragma unroll
    for (int im = 0; im < 2; im++)
#pragma unroll
        for (int in = 0; in < 4; in++) {
            int mo = m_blk + wm + im * 16 + (lane >> 2);
            int nn = n_blk + wn + in * 8 + ((lane & 3) << 1);
            *(float2*)&C[(size_t)mo * 512 + nn] = make_float2(acc[im][in][0], acc[im][in][1]);
            *(float2*)&C[(size_t)(mo + 8) * 512 + nn] = make_float2(acc[im][in][2], acc[im][in][3]);
        }
}

// ---------------- mma.sync fused causal attention (unchanged from R7 passing) ----------------
__global__ __launch_bounds__(256, 1) void attn_kernel()
{
    extern __shared__ __align__(16) char smc[];
    __nv_bfloat16* sQh  = (__nv_bfloat16*)(smc + OFF_QH);
    __nv_bfloat16* sQl  = (__nv_bfloat16*)(smc + OFF_QL);
    __nv_bfloat16* sKh  = (__nv_bfloat16*)(smc + OFF_KH);
    __nv_bfloat16* sKl  = (__nv_bfloat16*)(smc + OFF_KL);
    __nv_bfloat16* sVh  = (__nv_bfloat16*)(smc + OFF_VH);
    __nv_bfloat16* sVl  = (__nv_bfloat16*)(smc + OFF_VL);
    __nv_bfloat16* sRel = (__nv_bfloat16*)(smc + OFF_REL);
    __nv_bfloat16* sQe  = (__nv_bfloat16*)(smc + OFF_QE);
    float* s_t  = (float*)(smc + OFF_S);
    __nv_bfloat16* sPh  = (__nv_bfloat16*)(smc + OFF_PH);
    __nv_bfloat16* sPl  = (__nv_bfloat16*)(smc + OFF_PL);
    float* m_s  = (float*)(smc + OFF_STAT);
    float* ls_s = (float*)(smc + OFF_STAT + 256);
    float* al_s = (float*)(smc + OFF_STAT + 512);

    const int tid = threadIdx.x;
    const int wid = tid >> 5, lane = tid & 31;
    const int qi = blockIdx.x, bh = blockIdx.y;
    const int h = bh & 7, b = bh >> 3;
    const int i0 = qi * 64;
    const int wm = (wid >> 2) * 32;

#pragma unroll
    for (int it = 0; it < 2; it++) {
        int idx = tid + it * 256, r = idx >> 3, sg = idx & 7;
        size_t g = ((size_t)bh * 1024 + i0 + r) * 64 + sg * 8;
        *(uint4*)&sQh[r * 72 + sg * 8] = *(const uint4*)&g_Qh[g];
        *(uint4*)&sQl[r * 72 + sg * 8] = *(const uint4*)&g_Ql[g];
    }
    if (tid < 64) { m_s[tid] = -3.0e38f; ls_s[tid] = 0.f; }

    float acc_o[2][2][4] = {};
    const int ntiles = (i0 + 63) / 128 + 1;

    for (int jt = 0; jt < ntiles; jt++) {
        const int j0 = jt * 128;
        const int lmin = 960 - i0 + j0;
        __syncthreads();
#pragma unroll
        for (int it = 0; it < 4; it++) {
            int idx = tid + it * 256, t = idx >> 3, sg = idx & 7;
            size_t g = ((size_t)bh * 1024 + j0 + t) * 64 + sg * 8;
            *(uint4*)&sKh[t * 72 + sg * 8] = *(const uint4*)&g_Kh[g];
            *(uint4*)&sKl[t * 72 + sg * 8] = *(const uint4*)&g_Kl[g];
        }
#pragma unroll
        for (int it = 0; it < 4; it++) {
            int idx = tid + it * 256, dd = idx >> 4, sg = idx & 15;
            size_t g = ((size_t)bh * 64 + dd) * 1024 + j0 + sg * 8;
            *(uint4*)&sVh[dd * 136 + sg * 8] = *(const uint4*)&g_Vth[g];
            *(uint4*)&sVl[dd * 136 + sg * 8] = *(const uint4*)&g_Vtl[g];
        }
#pragma unroll
        for (int it = 0; it < 6; it++) {
            int idx = tid + it * 256, x = idx >> 3, sg = idx & 7;
            int l = lmin + x;
            uint4 v = make_uint4(0, 0, 0, 0);
            if (l <= 1023)
                v = *(const uint4*)&g_relT[((size_t)h * 1024 + l) * 64 + sg * 8];
            *(uint4*)&sRel[x * 72 + sg * 8] = v;
        }
        __syncthreads();

        // QE band GEMM (bf16 single)
        {
            const int wne = (wid & 3) * 48;
            float eacc[2][6][4] = {};
#pragma unroll
            for (int kk = 0; kk < 4; kk++) {
                uint32_t aq[2][4], br[3][4];
#pragma unroll
                for (int im = 0; im < 2; im++)
                    ldm_x4(aq[im], smaddr(&sQh[(wm + im * 16 + (lane & 15)) * 72 +
                                               ((lane >> 4) << 3) + kk * 16]));
#pragma unroll
                for (int bt = 0; bt < 3; bt++)
                    ldm_x4(br[bt], smaddr(&sRel[(wne + bt * 16 + ((lane >> 4) << 3) + (lane & 7)) * 72 +
                                                (((lane >> 3) & 1) << 3) + kk * 16]));
#pragma unroll
                for (int im = 0; im < 2; im++)
#pragma unroll
                    for (int in = 0; in < 6; in++) {
                        uint32_t b2[2] = { br[in >> 1][(in & 1) * 2], br[in >> 1][(in & 1) * 2 + 1] };
                        mma16816(eacc[im][in], aq[im], b2);
                    }
            }
#pragma unroll
            for (int im = 0; im < 2; im++)
#pragma unroll
                for (int in = 0; in < 6; in++) {
                    int i = wm + im * 16 + (lane >> 2);
                    int x = wne + in * 8 + ((lane & 3) << 1);
                    *(__nv_bfloat162*)&sQe[i * 200 + x] =
                        __nv_bfloat162(__float2bfloat16(eacc[im][in][0]),
                                       __float2bfloat16(eacc[im][in][1]));
                    *(__nv_bfloat162*)&sQe[(i + 8) * 200 + x] =
                        __nv_bfloat162(__float2bfloat16(eacc[im][in][2]),
                                       __float2bfloat16(eacc[im][in][3]));
                }
        }

        // QK^T (bf16x3)
        float acc[2][4][4] = {};
        {
            const int wn = (wid & 3) * 32;
#pragma unroll
            for (int kk = 0; kk < 4; kk++) {
                uint32_t ah[2][4], al[2][4], bhf[2][4], blf[2][4];
#pragma unroll
                for (int im = 0; im < 2; im++) {
                    int r = wm + im * 16 + (lane & 15);
                    int cc = ((lane >> 4) << 3) + kk * 16;
                    ldm_x4(ah[im], smaddr(&sQh[r * 72 + cc]));
                    ldm_x4(al[im], smaddr(&sQl[r * 72 + cc]));
                }
#pragma unroll
                for (int bt = 0; bt < 2; bt++) {
                    int r = wn + bt * 16 + ((lane >> 4) << 3) + (lane & 7);
                    int cc = (((lane >> 3) & 1) << 3) + kk * 16;
                    ldm_x4(bhf[bt], smaddr(&sKh[r * 72 + cc]));
                    ldm_x4(blf[bt], smaddr(&sKl[r * 72 + cc]));
                }
#pragma unroll
                for (int im = 0; im < 2; im++)
#pragma unroll
                    for (int in = 0; in < 4; in++) {
                        uint32_t b2h[2] = { bhf[in >> 1][(in & 1) * 2], bhf[in >> 1][(in & 1) * 2 + 1] };
                        uint32_t b2l[2] = { blf[in >> 1][(in & 1) * 2], blf[in >> 1][(in & 1) * 2 + 1] };
                        mma16816(acc[im][in], ah[im], b2h);
                        mma16816(acc[im][in], ah[im], b2l);
                        mma16816(acc[im][in], al[im], b2h);
                    }
            }
        }
        __syncthreads();

        // scores
        {
            const int wn = (wid & 3) * 32;
#pragma unroll
            for (int im = 0; im < 2; im++)
#pragma unroll
                for (int in = 0; in < 4; in++) {
#pragma unroll
                    for (int half = 0; half < 2; half++) {
                        int ii = wm + im * 16 + (lane >> 2) + half * 8;
                        float v0 = acc[im][in][half * 2], v1 = acc[im][in][half * 2 + 1];
                        int tt = wn + in * 8 + ((lane & 3) << 1);
                        float q0 = __bfloat162float(sQe[ii * 200 + (63 - ii + tt)]);
                        float q1 = __bfloat162float(sQe[ii * 200 + (63 - ii + tt + 1)]);
                        int ig = i0 + ii;
                        float m0 = (j0 + tt > ig) ? -1e9f : 0.f;
                        float m1 = (j0 + tt + 1 > ig) ? -1e9f : 0.f;
                        s_t[ii * 132 + tt]     = (v0 + q0 + m0) * 0.125f;
                        s_t[ii * 132 + tt + 1] = (v1 + q1 + m1) * 0.125f;
                    }
                }
        }
        __syncthreads();

        // online softmax
        {
            int row = tid >> 2, qq = tid & 3;
            float mloc = -3.0e38f;
#pragma unroll
            for (int cc = 0; cc < 32; cc++)
                mloc = fmaxf(mloc, s_t[row * 132 + qq + (cc << 2)]);
            mloc = fmaxf(mloc, __shfl_xor_sync(0xffffffffu, mloc, 1));
            mloc = fmaxf(mloc, __shfl_xor_sync(0xffffffffu, mloc, 2));
            float mold = m_s[row];
            float mnew = fmaxf(mold, mloc);
            float suml = 0.f;
#pragma unroll
            for (int cc = 0; cc < 32; cc++) {
                int col = qq + (cc << 2);
                float p = __expf(s_t[row * 132 + col] - mnew);
                suml += p;
                __nv_bfloat16 ph = __float2bfloat16(p);
                sPh[row * 136 + col] = ph;
                sPl[row * 136 + col] = __float2bfloat16(p - __bfloat162float(ph));
            }
            suml += __shfl_xor_sync(0xffffffffu, suml, 1);
            suml += __shfl_xor_sync(0xffffffffu, suml, 2);
            if (qq == 0) {
                float alpha = __expf(mold - mnew);
                al_s[row] = alpha;
                ls_s[row] = ls_s[row] * alpha + suml;
                m_s[row] = mnew;
            }
        }
        __syncthreads();

        // O = O*alpha + P @ V (bf16x3)
        {
            const int wnp = (wid & 3) * 16;
#pragma unroll
            for (int im = 0; im < 2; im++) {
                float a0 = al_s[wm + im * 16 + (lane >> 2)];
                float a1 = al_s[wm + im * 16 + (lane >> 2) + 8];
#pragma unroll
                for (int in = 0; in < 2; in++) {
                    acc_o[im][in][0] *= a0; acc_o[im][in][1] *= a0;
                    acc_o[im][in][2] *= a1; acc_o[im][in][3] *= a1;
                }
            }
#pragma unroll
            for (int kk = 0; kk < 8; kk++) {
                uint32_t ph[2][4], pl[2][4], bv[4], bvl[4];
#pragma unroll
                for (int im = 0; im < 2; im++) {
                    int r = wm + im * 16 + (lane & 15);
                    int cc = ((lane >> 4) << 3) + kk * 16;
                    ldm_x4(ph[im], smaddr(&sPh[r * 136 + cc]));
                    ldm_x4(pl[im], smaddr(&sPl[r * 136 + cc]));
                }
                {
                    int r = wnp + ((lane >> 4) << 3) + (lane & 7);
                    int cc = (((lane >> 3) & 1) << 3) + kk * 16;
                    ldm_x4(bv,  smaddr(&sVh[r * 136 + cc]));
                    ldm_x4(bvl, smaddr(&sVl[r * 136 + cc]));
                }
#pragma unroll
                for (int im = 0; im < 2; im++)
#pragma unroll
                    for (int in = 0; in < 2; in++) {
                        uint32_t b2h[2] = { bv[in * 2], bv[in * 2 + 1] };
                        uint32_t b2l[2] = { bvl[in * 2], bvl[in * 2 + 1] };
                        mma16816(acc_o[im][in], ph[im], b2h);
                        mma16816(acc_o[im][in], pl[im], b2h);
                        mma16816(acc_o[im][in], ph[im], b2l);
                    }
            }
        }
    }

    // epilogue
    {
        const int wnp = (wid & 3) * 16;
#pragma unroll
        for (int im = 0; im < 2; im++)
#pragma unroll
            for (int in = 0; in < 2; in++) {
                int i = wm + im * 16 + (lane >> 2);
                int d = wnp + in * 8 + ((lane & 3) << 1);
                float inv0 = 1.f / ls_s[i];
                float inv1 = 1.f / ls_s[i + 8];
                size_t o = (size_t)(b * 1024 + i0 + i) * 512 + h * 64 + d;
                __nv_bfloat162 h2, l2;
                split2(acc_o[im][in][0] * inv0, acc_o[im][in][1] * inv0, h2, l2);
                *(__nv_bfloat162*)&g_Ahi[o] = h2; *(__nv_bfloat162*)&g_Alo[o] = l2;
                split2(acc_o[im][in][2] * inv1, acc_o[im][in][3] * inv1, h2, l2);
                *(__nv_bfloat162*)&g_Ahi[o + 8 * 512] = h2;
                *(__nv_bfloat162*)&g_Alo[o + 8 * 512] = l2;
            }
    }
}

// ---------------- host ----------------
extern "C" void kernel_launch(void* const* d_in, const int* in_sizes, int n_in,
                              void* d_out, int out_size)
{
    const float* queries = (const float*)d_in[0];
    const float* keys    = (const float*)d_in[1];
    const float* values  = (const float*)d_in[2];
    const float* Wq = (const float*)d_in[4];
    const float* Wk = (const float*)d_in[5];
    const float* Wv = (const float*)d_in[6];
    const float* Wo = (const float*)d_in[7];
    const float* rel = (const float*)d_in[8];
    float* out = (float*)d_out;

    __nv_bfloat16 *pWh, *pWl, *pRT;
    cudaGetSymbolAddress((void**)&pWh, g_Whi);
    cudaGetSymbolAddress((void**)&pWl, g_Wlo);
    cudaGetSymbolAddress((void**)&pRT, g_relT);

    cudaFuncSetAttribute(attn_kernel, cudaFuncAttributeMaxDynamicSharedMemorySize, ATTN_SMEM);

    const int N4 = 4096 * 512 / 4;
    dim3 cgrid((N4 + 255) / 256, 3), cblk(256);
    dim3 wgrid(16, 16, 4), wblk(32, 8);
    dim3 rgrid(32, 2, 8);

    conv_wt<<<wgrid, wblk>>>(Wq, Wk, Wv, Wo, pWh, pWl);
    conv_rel<<<rgrid, wblk>>>(rel, pRT);
    conv_act3<<<cgrid, cblk>>>(queries, keys, values, N4);

    dim3 qkvgrid(8, 64, 3), gblk(128);
    gemm_qkv<<<qkvgrid, gblk>>>();

    dim3 ga(16, 32), tb(256);
    attn_kernel<<<ga, tb, ATTN_SMEM>>>();

    dim3 ogrid(8, 64);
    gemm_out<<<ogrid, gblk>>>(out);
}

// round 10
// speedup vs baseline: 2.8353x; 1.1159x over previous
#include <cuda_runtime.h>
#include <cuda_bf16.h>
#include <cstdint>

#define S_LEN 1024
#define DHDIM 64
#define NHEADS 8
#define NBATCH 4
#define BHN (NBATCH * NHEADS)
#define LDA 40

// attn smem byte offsets
#define OFF_QH 0
#define OFF_QL 9216
#define OFF_KH 18432
#define OFF_KL 36864
#define OFF_VH 55296
#define OFF_VL 72704
#define OFF_REL 90112
#define OFF_QE 117760
#define OFF_REDA 143360
#define OFF_REDB 144384
#define OFF_STAT 145408
#define OFF_EPI OFF_KH          // overlay: used only after tile loop
#define ATTN_SMEM 145920

// ---------------- scratch ----------------
__device__ __nv_bfloat16 g_Ahi[4096 * 512];     // ctx hi -> final gemm
__device__ __nv_bfloat16 g_Alo[4096 * 512];
__device__ __nv_bfloat16 g_A0h[4096 * 512];
__device__ __nv_bfloat16 g_A0l[4096 * 512];
__device__ __nv_bfloat16 g_A1h[4096 * 512];
__device__ __nv_bfloat16 g_A1l[4096 * 512];
__device__ __nv_bfloat16 g_A2h[4096 * 512];
__device__ __nv_bfloat16 g_A2l[4096 * 512];
__device__ __nv_bfloat16 g_Whi[4 * 512 * 512];
__device__ __nv_bfloat16 g_Wlo[4 * 512 * 512];
__device__ __nv_bfloat16 g_Qh[BHN * S_LEN * DHDIM];
__device__ __nv_bfloat16 g_Ql[BHN * S_LEN * DHDIM];
__device__ __nv_bfloat16 g_Kh[BHN * S_LEN * DHDIM];
__device__ __nv_bfloat16 g_Kl[BHN * S_LEN * DHDIM];
__device__ __nv_bfloat16 g_Vth[BHN * DHDIM * S_LEN];   // [bh][d][t]
__device__ __nv_bfloat16 g_Vtl[BHN * DHDIM * S_LEN];
__device__ __nv_bfloat16 g_relT[NHEADS * S_LEN * DHDIM]; // [h][l][d]

// ---------------- helpers ----------------
__device__ __forceinline__ uint32_t smaddr(const void* p) {
    return (uint32_t)__cvta_generic_to_shared(p);
}
#define CP16(dst, src) \
    asm volatile("cp.async.cg.shared.global [%0], [%1], 16;" :: "r"(dst), "l"(src))

__device__ __forceinline__ void ldm_x4(uint32_t* r, uint32_t a) {
    asm volatile("ldmatrix.sync.aligned.m8n8.x4.shared.b16 {%0,%1,%2,%3}, [%4];"
                 : "=r"(r[0]), "=r"(r[1]), "=r"(r[2]), "=r"(r[3]) : "r"(a));
}
__device__ __forceinline__ void mma16816(float* c, const uint32_t* a, const uint32_t* b) {
    asm volatile("mma.sync.aligned.m16n8k16.row.col.f32.bf16.bf16.f32 "
                 "{%0,%1,%2,%3}, {%4,%5,%6,%7}, {%8,%9}, {%0,%1,%2,%3};"
                 : "+f"(c[0]), "+f"(c[1]), "+f"(c[2]), "+f"(c[3])
                 : "r"(a[0]), "r"(a[1]), "r"(a[2]), "r"(a[3]), "r"(b[0]), "r"(b[1]));
}
__device__ __forceinline__ void split2(float v0, float v1,
                                       __nv_bfloat162& h2, __nv_bfloat162& l2) {
    __nv_bfloat16 h0 = __float2bfloat16(v0), h1 = __float2bfloat16(v1);
    h2 = __nv_bfloat162(h0, h1);
    l2 = __nv_bfloat162(__float2bfloat16(v0 - __bfloat162float(h0)),
                        __float2bfloat16(v1 - __bfloat162float(h1)));
}
__device__ __forceinline__ uint32_t pack_split(float v0, float v1, uint32_t& lo) {
    __nv_bfloat162 h2, l2;
    split2(v0, v1, h2, l2);
    lo = *(uint32_t*)&l2;
    return *(uint32_t*)&h2;
}

// ---------------- convert kernels ----------------
__global__ void conv_act3(const float* __restrict__ q, const float* __restrict__ k,
                          const float* __restrict__ v, int n4) {
    int i = blockIdx.x * blockDim.x + threadIdx.x;
    if (i >= n4) return;
    int w = blockIdx.y;
    const float* x = (w == 0) ? q : (w == 1) ? k : v;
    __nv_bfloat16* hi = (w == 0) ? g_A0h : (w == 1) ? g_A1h : g_A2h;
    __nv_bfloat16* lo = (w == 0) ? g_A0l : (w == 1) ? g_A1l : g_A2l;
    float4 val = ((const float4*)x)[i];
    __nv_bfloat162 h2a, l2a, h2b, l2b;
    split2(val.x, val.y, h2a, l2a);
    split2(val.z, val.w, h2b, l2b);
    ((__nv_bfloat162*)hi)[2 * i] = h2a; ((__nv_bfloat162*)hi)[2 * i + 1] = h2b;
    ((__nv_bfloat162*)lo)[2 * i] = l2a; ((__nv_bfloat162*)lo)[2 * i + 1] = l2b;
}

// z<4: weight transpose+split; z=4,5: rel transpose
__global__ void conv_misc(const float* __restrict__ W0, const float* __restrict__ W1,
                          const float* __restrict__ W2, const float* __restrict__ W3,
                          const float* __restrict__ rel) {
    __shared__ float t[32][33];
    int z = blockIdx.z;
    int tx = threadIdx.x, ty = threadIdx.y;
    if (z < 4) {
        const float* W = (z == 0) ? W0 : (z == 1) ? W1 : (z == 2) ? W2 : W3;
        int bx = blockIdx.x, by = blockIdx.y;
#pragma unroll
        for (int j = 0; j < 32; j += 8)
            t[ty + j][tx] = W[(size_t)(by * 32 + ty + j) * 512 + bx * 32 + tx];
        __syncthreads();
        size_t base = (size_t)z * 512 * 512;
#pragma unroll
        for (int j = 0; j < 32; j += 8) {
            float v = t[tx][ty + j];
            __nv_bfloat16 h = __float2bfloat16(v);
            size_t o = base + (size_t)(bx * 32 + ty + j) * 512 + by * 32 + tx;
            g_Whi[o] = h;
            g_Wlo[o] = __float2bfloat16(v - __bfloat162float(h));
        }
    } else {
        int d0 = (z - 4) * 32;
        int idx = blockIdx.y * 16 + blockIdx.x;
        int hh = idx >> 5, l0 = (idx & 31) * 32;
#pragma unroll
        for (int j = 0; j < 32; j += 8)
            t[ty + j][tx] = rel[(size_t)(hh * 64 + d0 + ty + j) * 1024 + l0 + tx];
        __syncthreads();
#pragma unroll
        for (int j = 0; j < 32; j += 8)
            g_relT[(size_t)(hh * 1024 + l0 + ty + j) * 64 + d0 + tx] =
                __float2bfloat16(t[tx][ty + j]);
    }
}

// ---------------- merged QKV projection GEMM (unchanged mainloop) ----------------
__global__ __launch_bounds__(128) void gemm_qkv()
{
    __shared__ __nv_bfloat16 sA[2][2][64 * LDA];
    __shared__ __nv_bfloat16 sB[2][2][64 * LDA];
    const int z = blockIdx.z;
    const __nv_bfloat16* Ah = (z == 0) ? g_A0h : (z == 1) ? g_A1h : g_A2h;
    const __nv_bfloat16* Al = (z == 0) ? g_A0l : (z == 1) ? g_A1l : g_A2l;
    const __nv_bfloat16* Bh = g_Whi + (size_t)z * 512 * 512;
    const __nv_bfloat16* Bl = g_Wlo + (size_t)z * 512 * 512;
    const int tid = threadIdx.x;
    const int wid = tid >> 5, lane = tid & 31;
    const int m_blk = blockIdx.y * 64, n_blk = blockIdx.x * 64;
    const int wm = (wid >> 1) * 32, wn = (wid & 1) * 32;

    float acc[2][4][4] = {};

    auto load_stage = [&](int stg, int k0) {
        int st = stg & 1;
        int r1 = tid >> 2, sg = tid & 3;
#pragma unroll
        for (int i = 0; i < 2; i++) {
            int r = r1 + i * 32;
            uint32_t off = (uint32_t)(r * LDA + sg * 8) * 2;
            size_t gA = (size_t)(m_blk + r) * 512 + k0 + sg * 8;
            size_t gB = (size_t)(n_blk + r) * 512 + k0 + sg * 8;
            CP16(smaddr(&sA[st][0][0]) + off, Ah + gA);
            CP16(smaddr(&sA[st][1][0]) + off, Al + gA);
            CP16(smaddr(&sB[st][0][0]) + off, Bh + gB);
            CP16(smaddr(&sB[st][1][0]) + off, Bl + gB);
        }
    };

    load_stage(0, 0);
    asm volatile("cp.async.commit_group;");

    for (int s = 0; s < 16; s++) {
        if (s < 15) {
            load_stage(s + 1, (s + 1) * 32);
            asm volatile("cp.async.commit_group;");
            asm volatile("cp.async.wait_group 1;");
        } else {
            asm volatile("cp.async.wait_group 0;");
        }
        __syncthreads();
        int st = s & 1;
#pragma unroll
        for (int kk = 0; kk < 2; kk++) {
            uint32_t ah[2][4], al[2][4], bhf[2][4], blf[2][4];
#pragma unroll
            for (int im = 0; im < 2; im++) {
                int r = wm + im * 16 + (lane & 15);
                int cc = ((lane >> 4) << 3) + kk * 16;
                ldm_x4(ah[im], smaddr(&sA[st][0][r * LDA + cc]));
                ldm_x4(al[im], smaddr(&sA[st][1][r * LDA + cc]));
            }
#pragma unroll
            for (int bt = 0; bt < 2; bt++) {
                int r = wn + bt * 16 + ((lane >> 4) << 3) + (lane & 7);
                int cc = (((lane >> 3) & 1) << 3) + kk * 16;
                ldm_x4(bhf[bt], smaddr(&sB[st][0][r * LDA + cc]));
                ldm_x4(blf[bt], smaddr(&sB[st][1][r * LDA + cc]));
            }
#pragma unroll
            for (int im = 0; im < 2; im++)
#pragma unroll
                for (int in = 0; in < 4; in++) {
                    uint32_t bh2[2] = { bhf[in >> 1][(in & 1) * 2], bhf[in >> 1][(in & 1) * 2 + 1] };
                    uint32_t bl2[2] = { blf[in >> 1][(in & 1) * 2], blf[in >> 1][(in & 1) * 2 + 1] };
                    mma16816(acc[im][in], ah[im], bh2);
                    mma16816(acc[im][in], ah[im], bl2);
                    mma16816(acc[im][in], al[im], bh2);
                }
        }
        __syncthreads();
    }

    __nv_bfloat16* Chi = (z == 0) ? g_Qh : (z == 1) ? g_Kh : g_Vth;
    __nv_bfloat16* Clo = (z == 0) ? g_Ql : (z == 1) ? g_Kl : g_Vtl;
#pragma unroll
    for (int im = 0; im < 2; im++)
#pragma unroll
        for (int in = 0; in < 4; in++) {
            int mo = m_blk + wm + im * 16 + (lane >> 2);
            int nn = n_blk + wn + in * 8 + ((lane & 3) << 1);
            float c0 = acc[im][in][0], c1 = acc[im][in][1];
            float c2 = acc[im][in][2], c3 = acc[im][in][3];
            int b = mo >> 10, ss = mo & 1023, hh = nn >> 6, dh = nn & 63;
            if (z < 2) {
                size_t o = ((size_t)(b * 8 + hh) * 1024 + ss) * 64 + dh;
                __nv_bfloat162 h2, l2;
                split2(c0, c1, h2, l2);
                *(__nv_bfloat162*)&Chi[o] = h2; *(__nv_bfloat162*)&Clo[o] = l2;
                split2(c2, c3, h2, l2);
                *(__nv_bfloat162*)&Chi[o + 8 * 64] = h2; *(__nv_bfloat162*)&Clo[o + 8 * 64] = l2;
            } else {
                size_t o = ((size_t)(b * 8 + hh) * 64 + dh) * 1024 + ss;
                __nv_bfloat16 h;
                h = __float2bfloat16(c0); Chi[o] = h;
                Clo[o] = __float2bfloat16(c0 - __bfloat162float(h));
                h = __float2bfloat16(c1); Chi[o + 1024] = h;
                Clo[o + 1024] = __float2bfloat16(c1 - __bfloat162float(h));
                h = __float2bfloat16(c2); Chi[o + 8] = h;
                Clo[o + 8] = __float2bfloat16(c2 - __bfloat162float(h));
                h = __float2bfloat16(c3); Chi[o + 1024 + 8] = h;
                Clo[o + 1024 + 8] = __float2bfloat16(c3 - __bfloat162float(h));
            }
        }
}

// ---------------- output GEMM (unchanged) ----------------
__global__ __launch_bounds__(128) void gemm_out(float* __restrict__ C)
{
    __shared__ __nv_bfloat16 sA[2][2][64 * LDA];
    __shared__ __nv_bfloat16 sB[2][2][64 * LDA];
    const __nv_bfloat16* Ah = g_Ahi;
    const __nv_bfloat16* Al = g_Alo;
    const __nv_bfloat16* Bh = g_Whi + (size_t)3 * 512 * 512;
    const __nv_bfloat16* Bl = g_Wlo + (size_t)3 * 512 * 512;
    const int tid = threadIdx.x;
    const int wid = tid >> 5, lane = tid & 31;
    const int m_blk = blockIdx.y * 64, n_blk = blockIdx.x * 64;
    const int wm = (wid >> 1) * 32, wn = (wid & 1) * 32;

    float acc[2][4][4] = {};

    auto load_stage = [&](int stg, int k0) {
        int st = stg & 1;
        int r1 = tid >> 2, sg = tid & 3;
#pragma unroll
        for (int i = 0; i < 2; i++) {
            int r = r1 + i * 32;
            uint32_t off = (uint32_t)(r * LDA + sg * 8) * 2;
            size_t gA = (size_t)(m_blk + r) * 512 + k0 + sg * 8;
            size_t gB = (size_t)(n_blk + r) * 512 + k0 + sg * 8;
            CP16(smaddr(&sA[st][0][0]) + off, Ah + gA);
            CP16(smaddr(&sA[st][1][0]) + off, Al + gA);
            CP16(smaddr(&sB[st][0][0]) + off, Bh + gB);
            CP16(smaddr(&sB[st][1][0]) + off, Bl + gB);
        }
    };

    load_stage(0, 0);
    asm volatile("cp.async.commit_group;");

    for (int s = 0; s < 16; s++) {
        if (s < 15) {
            load_stage(s + 1, (s + 1) * 32);
            asm volatile("cp.async.commit_group;");
            asm volatile("cp.async.wait_group 1;");
        } else {
            asm volatile("cp.async.wait_group 0;");
        }
        __syncthreads();
        int st = s & 1;
#pragma unroll
        for (int kk = 0; kk < 2; kk++) {
            uint32_t ah[2][4], al[2][4], bhf[2][4], blf[2][4];
#pragma unroll
            for (int im = 0; im < 2; im++) {
                int r = wm + im * 16 + (lane & 15);
                int cc = ((lane >> 4) << 3) + kk * 16;
                ldm_x4(ah[im], smaddr(&sA[st][0][r * LDA + cc]));
                ldm_x4(al[im], smaddr(&sA[st][1][r * LDA + cc]));
            }
#pragma unroll
            for (int bt = 0; bt < 2; bt++) {
                int r = wn + bt * 16 + ((lane >> 4) << 3) + (lane & 7);
                int cc = (((lane >> 3) & 1) << 3) + kk * 16;
                ldm_x4(bhf[bt], smaddr(&sB[st][0][r * LDA + cc]));
                ldm_x4(blf[bt], smaddr(&sB[st][1][r * LDA + cc]));
            }
#pragma unroll
            for (int im = 0; im < 2; im++)
#pragma unroll
                for (int in = 0; in < 4; in++) {
                    uint32_t bh2[2] = { bhf[in >> 1][(in & 1) * 2], bhf[in >> 1][(in & 1) * 2 + 1] };
                    uint32_t bl2[2] = { blf[in >> 1][(in & 1) * 2], blf[in >> 1][(in & 1) * 2 + 1] };
                    mma16816(acc[im][in], ah[im], bh2);
                    mma16816(acc[im][in], ah[im], bl2);
                    mma16816(acc[im][in], al[im], bh2);
                }
        }
        __syncthreads();
    }

#pragma unroll
    for (int im = 0; im < 2; im++)
#pragma unroll
        for (int in = 0; in < 4; in++) {
            int mo = m_blk + wm + im * 16 + (lane >> 2);
            int nn = n_blk + wn + in * 8 + ((lane & 3) << 1);
            *(float2*)&C[(size_t)mo * 512 + nn] = make_float2(acc[im][in][0], acc[im][in][1]);
            *(float2*)&C[(size_t)(mo + 8) * 512 + nn] = make_float2(acc[im][in][2], acc[im][in][3]);
        }
}

// ---------------- fused attention, register-resident softmax ----------------
__global__ __launch_bounds__(256, 1) void attn_kernel()
{
    extern __shared__ __align__(16) char smc[];
    __nv_bfloat16* sQh  = (__nv_bfloat16*)(smc + OFF_QH);   // [64][72]
    __nv_bfloat16* sQl  = (__nv_bfloat16*)(smc + OFF_QL);
    __nv_bfloat16* sKh  = (__nv_bfloat16*)(smc + OFF_KH);   // [128][72]
    __nv_bfloat16* sKl  = (__nv_bfloat16*)(smc + OFF_KL);
    __nv_bfloat16* sVh  = (__nv_bfloat16*)(smc + OFF_VH);   // [64 d][136 t]
    __nv_bfloat16* sVl  = (__nv_bfloat16*)(smc + OFF_VL);
    __nv_bfloat16* sRel = (__nv_bfloat16*)(smc + OFF_REL);  // [192 x][72 d]
    __nv_bfloat16* sQe  = (__nv_bfloat16*)(smc + OFF_QE);   // [64][200]
    float* sRedA = (float*)(smc + OFF_REDA);                // [8][32]
    float* sRedB = (float*)(smc + OFF_REDB);                // [8][32]
    float* m_s   = (float*)(smc + OFF_STAT);                // [64]
    float* ls_s  = (float*)(smc + OFF_STAT + 256);          // [64]

    const int tid = threadIdx.x;
    const int wid = tid >> 5, lane = tid & 31;
    const int qi = 15 - blockIdx.x;       // heavy blocks first
    const int bh = blockIdx.y;
    const int h = bh & 7, b = bh >> 3;
    const int i0 = qi * 64;
    const int wm = (wid >> 2) * 32;       // warp row block
    const int wn = (wid & 3) * 32;        // warp key block
    const int gbase = (wid >> 2) * 4;     // first warp of my row group
    const int rl = lane >> 2;
    const int qoff = (lane & 3) << 1;

#pragma unroll
    for (int it = 0; it < 2; it++) {
        int idx = tid + it * 256, r = idx >> 3, sg = idx & 7;
        size_t g = ((size_t)bh * 1024 + i0 + r) * 64 + sg * 8;
        *(uint4*)&sQh[r * 72 + sg * 8] = *(const uint4*)&g_Qh[g];
        *(uint4*)&sQl[r * 72 + sg * 8] = *(const uint4*)&g_Ql[g];
    }
    if (tid < 64) { m_s[tid] = -3.0e38f; ls_s[tid] = 0.f; }

    float acc_o[2][8][4] = {};            // [im][d8-block][4]: full d=64, my key slice
    const int ntiles = (i0 + 63) / 128 + 1;

    for (int jt = 0; jt < ntiles; jt++) {
        const int j0 = jt * 128;
        const int lmin = 960 - i0 + j0;
        __syncthreads();
#pragma unroll
        for (int it = 0; it < 4; it++) {
            int idx = tid + it * 256, t = idx >> 3, sg = idx & 7;
            size_t g = ((size_t)bh * 1024 + j0 + t) * 64 + sg * 8;
            *(uint4*)&sKh[t * 72 + sg * 8] = *(const uint4*)&g_Kh[g];
            *(uint4*)&sKl[t * 72 + sg * 8] = *(const uint4*)&g_Kl[g];
        }
#pragma unroll
        for (int it = 0; it < 4; it++) {
            int idx = tid + it * 256, dd = idx >> 4, sg = idx & 15;
            size_t g = ((size_t)bh * 64 + dd) * 1024 + j0 + sg * 8;
            *(uint4*)&sVh[dd * 136 + sg * 8] = *(const uint4*)&g_Vth[g];
            *(uint4*)&sVl[dd * 136 + sg * 8] = *(const uint4*)&g_Vtl[g];
        }
#pragma unroll
        for (int it = 0; it < 6; it++) {
            int idx = tid + it * 256, x = idx >> 3, sg = idx & 7;
            int l = lmin + x;
            uint4 v = make_uint4(0, 0, 0, 0);
            if (l <= 1023)
                v = *(const uint4*)&g_relT[((size_t)h * 1024 + l) * 64 + sg * 8];
            *(uint4*)&sRel[x * 72 + sg * 8] = v;
        }
        __syncthreads();

        // ---- QE band GEMM (single bf16) -> sQe ----
        {
            const int wne = (wid & 3) * 48;
            float eacc[2][6][4] = {};
#pragma unroll
            for (int kk = 0; kk < 4; kk++) {
                uint32_t aq[2][4], br[3][4];
#pragma unroll
                for (int im = 0; im < 2; im++)
                    ldm_x4(aq[im], smaddr(&sQh[(wm + im * 16 + (lane & 15)) * 72 +
                                               ((lane >> 4) << 3) + kk * 16]));
#pragma unroll
                for (int bt = 0; bt < 3; bt++)
                    ldm_x4(br[bt], smaddr(&sRel[(wne + bt * 16 + ((lane >> 4) << 3) + (lane & 7)) * 72 +
                                                (((lane >> 3) & 1) << 3) + kk * 16]));
#pragma unroll
                for (int im = 0; im < 2; im++)
#pragma unroll
                    for (int in = 0; in < 6; in++) {
                        uint32_t b2[2] = { br[in >> 1][(in & 1) * 2], br[in >> 1][(in & 1) * 2 + 1] };
                        mma16816(eacc[im][in], aq[im], b2);
                    }
            }
#pragma unroll
            for (int im = 0; im < 2; im++)
#pragma unroll
                for (int in = 0; in < 6; in++) {
                    int i = wm + im * 16 + rl;
                    int x = wne + in * 8 + qoff;
                    *(__nv_bfloat162*)&sQe[i * 200 + x] =
                        __nv_bfloat162(__float2bfloat16(eacc[im][in][0]),
                                       __float2bfloat16(eacc[im][in][1]));
                    *(__nv_bfloat162*)&sQe[(i + 8) * 200 + x] =
                        __nv_bfloat162(__float2bfloat16(eacc[im][in][2]),
                                       __float2bfloat16(eacc[im][in][3]));
                }
        }

        // ---- QK^T (bf16x3) -> acc regs ----
        float acc[2][4][4] = {};
#pragma unroll
        for (int kk = 0; kk < 4; kk++) {
            uint32_t ah[2][4], al[2][4], bhf[2][4], blf[2][4];
#pragma unroll
            for (int im = 0; im < 2; im++) {
                int r = wm + im * 16 + (lane & 15);
                int cc = ((lane >> 4) << 3) + kk * 16;
                ldm_x4(ah[im], smaddr(&sQh[r * 72 + cc]));
                ldm_x4(al[im], smaddr(&sQl[r * 72 + cc]));
            }
#pragma unroll
            for (int bt = 0; bt < 2; bt++) {
                int r = wn + bt * 16 + ((lane >> 4) << 3) + (lane & 7);
                int cc = (((lane >> 3) & 1) << 3) + kk * 16;
                ldm_x4(bhf[bt], smaddr(&sKh[r * 72 + cc]));
                ldm_x4(blf[bt], smaddr(&sKl[r * 72 + cc]));
            }
#pragma unroll
            for (int im = 0; im < 2; im++)
#pragma unroll
                for (int in = 0; in < 4; in++) {
                    uint32_t b2h[2] = { bhf[in >> 1][(in & 1) * 2], bhf[in >> 1][(in & 1) * 2 + 1] };
                    uint32_t b2l[2] = { blf[in >> 1][(in & 1) * 2], blf[in >> 1][(in & 1) * 2 + 1] };
                    mma16816(acc[im][in], ah[im], b2h);
                    mma16816(acc[im][in], ah[im], b2l);
                    mma16816(acc[im][in], al[im], b2h);
                }
        }
        __syncthreads();   // sQe ready

        // ---- scores (regs): gather qe, mask, scale; partial row max ----
        float mold[2][2], lsold[2][2];
#pragma unroll
        for (int im = 0; im < 2; im++)
#pragma unroll
            for (int hf = 0; hf < 2; hf++) {
                int row = wm + im * 16 + rl + hf * 8;
                mold[im][hf] = m_s[row];
                lsold[im][hf] = ls_s[row];
            }
        float pmax[2][2] = {{-3.0e38f, -3.0e38f}, {-3.0e38f, -3.0e38f}};
#pragma unroll
        for (int im = 0; im < 2; im++)
#pragma unroll
            for (int in = 0; in < 4; in++)
#pragma unroll
                for (int hf = 0; hf < 2; hf++) {
                    int iiq = wm + im * 16 + rl + hf * 8;
                    int tt = wn + in * 8 + qoff;
                    float q0 = __bfloat162float(sQe[iiq * 200 + (63 - iiq + tt)]);
                    float q1 = __bfloat162float(sQe[iiq * 200 + (63 - iiq + tt + 1)]);
                    float m0 = (j0 + tt     > i0 + iiq) ? -1e9f : 0.f;
                    float m1 = (j0 + tt + 1 > i0 + iiq) ? -1e9f : 0.f;
                    float s0 = (acc[im][in][hf * 2]     + q0 + m0) * 0.125f;
                    float s1 = (acc[im][in][hf * 2 + 1] + q1 + m1) * 0.125f;
                    acc[im][in][hf * 2] = s0;
                    acc[im][in][hf * 2 + 1] = s1;
                    pmax[im][hf] = fmaxf(pmax[im][hf], fmaxf(s0, s1));
                }
#pragma unroll
        for (int im = 0; im < 2; im++)
#pragma unroll
            for (int hf = 0; hf < 2; hf++) {
                pmax[im][hf] = fmaxf(pmax[im][hf], __shfl_xor_sync(0xffffffffu, pmax[im][hf], 1));
                pmax[im][hf] = fmaxf(pmax[im][hf], __shfl_xor_sync(0xffffffffu, pmax[im][hf], 2));
            }
        if ((lane & 3) == 0) {
#pragma unroll
            for (int im = 0; im < 2; im++)
#pragma unroll
                for (int hf = 0; hf < 2; hf++)
                    sRedA[wid * 32 + im * 16 + rl + hf * 8] = pmax[im][hf];
        }
        __syncthreads();

        // ---- global row max, exp in regs, partial sums ----
        float mnew[2][2], alpha[2][2], psum[2][2] = {};
#pragma unroll
        for (int im = 0; im < 2; im++)
#pragma unroll
            for (int hf = 0; hf < 2; hf++) {
                int loc = im * 16 + rl + hf * 8;
                float mm = mold[im][hf];
#pragma unroll
                for (int j = 0; j < 4; j++)
                    mm = fmaxf(mm, sRedA[(gbase + j) * 32 + loc]);
                mnew[im][hf] = mm;
                alpha[im][hf] = __expf(mold[im][hf] - mm);
            }
#pragma unroll
        for (int im = 0; im < 2; im++)
#pragma unroll
            for (int in = 0; in < 4; in++)
#pragma unroll
                for (int hf = 0; hf < 2; hf++) {
                    float p0 = __expf(acc[im][in][hf * 2]     - mnew[im][hf]);
                    float p1 = __expf(acc[im][in][hf * 2 + 1] - mnew[im][hf]);
                    acc[im][in][hf * 2] = p0;
                    acc[im][in][hf * 2 + 1] = p1;
                    psum[im][hf] += p0 + p1;
                }
#pragma unroll
        for (int im = 0; im < 2; im++)
#pragma unroll
            for (int hf = 0; hf < 2; hf++) {
                psum[im][hf] += __shfl_xor_sync(0xffffffffu, psum[im][hf], 1);
                psum[im][hf] += __shfl_xor_sync(0xffffffffu, psum[im][hf], 2);
            }
        if ((lane & 3) == 0) {
#pragma unroll
            for (int im = 0; im < 2; im++)
#pragma unroll
                for (int hf = 0; hf < 2; hf++)
                    sRedB[wid * 32 + im * 16 + rl + hf * 8] = psum[im][hf];
        }

        // rescale O by alpha
#pragma unroll
        for (int im = 0; im < 2; im++)
#pragma unroll
            for (int d8 = 0; d8 < 8; d8++) {
                acc_o[im][d8][0] *= alpha[im][0];
                acc_o[im][d8][1] *= alpha[im][0];
                acc_o[im][d8][2] *= alpha[im][1];
                acc_o[im][d8][3] *= alpha[im][1];
            }

        // build P fragments (C-layout == A-layout)
        uint32_t aph[2][2][4], apl[2][2][4];
#pragma unroll
        for (int im = 0; im < 2; im++)
#pragma unroll
            for (int kb = 0; kb < 2; kb++) {
                aph[im][kb][0] = pack_split(acc[im][2 * kb][0],     acc[im][2 * kb][1],     apl[im][kb][0]);
                aph[im][kb][1] = pack_split(acc[im][2 * kb][2],     acc[im][2 * kb][3],     apl[im][kb][1]);
                aph[im][kb][2] = pack_split(acc[im][2 * kb + 1][0], acc[im][2 * kb + 1][1], apl[im][kb][2]);
                aph[im][kb][3] = pack_split(acc[im][2 * kb + 1][2], acc[im][2 * kb + 1][3], apl[im][kb][3]);
            }
        __syncthreads();

        // totals + stat writers (warps 0 and 4, lane quads 0)
        if ((wid & 3) == 0 && (lane & 3) == 0) {
#pragma unroll
            for (int im = 0; im < 2; im++)
#pragma unroll
                for (int hf = 0; hf < 2; hf++) {
                    int loc = im * 16 + rl + hf * 8;
                    float tot = 0.f;
#pragma unroll
                    for (int j = 0; j < 4; j++)
                        tot += sRedB[(gbase + j) * 32 + loc];
                    m_s[wm + loc] = mnew[im][hf];
                    ls_s[wm + loc] = lsold[im][hf] * alpha[im][hf] + tot;
                }
        }

        // ---- P @ V (bf16x3), P from registers, V n-dim = d ----
#pragma unroll
        for (int kb = 0; kb < 2; kb++) {
            uint32_t bvh[4][4], bvl[4][4];
#pragma unroll
            for (int dn = 0; dn < 4; dn++) {
                int r = dn * 16 + ((lane >> 4) << 3) + (lane & 7);
                int cc = (((lane >> 3) & 1) << 3) + wn + kb * 16;
                ldm_x4(bvh[dn], smaddr(&sVh[r * 136 + cc]));
                ldm_x4(bvl[dn], smaddr(&sVl[r * 136 + cc]));
            }
#pragma unroll
            for (int im = 0; im < 2; im++)
#pragma unroll
                for (int d8 = 0; d8 < 8; d8++) {
                    uint32_t b2h[2] = { bvh[d8 >> 1][(d8 & 1) * 2], bvh[d8 >> 1][(d8 & 1) * 2 + 1] };
                    uint32_t b2l[2] = { bvl[d8 >> 1][(d8 & 1) * 2], bvl[d8 >> 1][(d8 & 1) * 2 + 1] };
                    mma16816(acc_o[im][d8], aph[im][kb], b2h);
                    mma16816(acc_o[im][d8], apl[im][kb], b2h);
                    mma16816(acc_o[im][d8], aph[im][kb], b2l);
                }
        }
    }

    // ---- epilogue: cross-warp O reduction over key slices ----
    __syncthreads();
    float* sEpi = (float*)(smc + OFF_EPI);   // [8 warps][32 rows][64 d]
#pragma unroll
    for (int im = 0; im < 2; im++)
#pragma unroll
        for (int d8 = 0; d8 < 8; d8++)
#pragma unroll
            for (int e = 0; e < 4; e++) {
                int loc = im * 16 + rl + (e >> 1) * 8;
                int d = d8 * 8 + qoff + (e & 1);
                sEpi[(wid * 32 + loc) * 64 + d] = acc_o[im][d8][e];
            }
    __syncthreads();
#pragma unroll
    for (int u = 0; u < 8; u++) {
        int idx2 = tid * 8 + u;
        int r = idx2 >> 5;
        int d = (idx2 & 31) * 2;
        int gg = r >> 5, loc = r & 31;
        float s0 = 0.f, s1 = 0.f;
#pragma unroll
        for (int j = 0; j < 4; j++) {
            const float* pp = &sEpi[((gg * 4 + j) * 32 + loc) * 64 + d];
            s0 += pp[0];
            s1 += pp[1];
        }
        float inv = 1.f / ls_s[r];
        __nv_bfloat162 h2, l2;
        split2(s0 * inv, s1 * inv, h2, l2);
        size_t o = (size_t)(b * 1024 + i0 + r) * 512 + h * 64 + d;
        *(__nv_bfloat162*)&g_Ahi[o] = h2;
        *(__nv_bfloat162*)&g_Alo[o] = l2;
    }
}

// ---------------- host ----------------
extern "C" void kernel_launch(void* const* d_in, const int* in_sizes, int n_in,
                              void* d_out, int out_size)
{
    const float* queries = (const float*)d_in[0];
    const float* keys    = (const float*)d_in[1];
    const float* values  = (const float*)d_in[2];
    const float* Wq = (const float*)d_in[4];
    const float* Wk = (const float*)d_in[5];
    const float* Wv = (const float*)d_in[6];
    const float* Wo = (const float*)d_in[7];
    const float* rel = (const float*)d_in[8];
    float* out = (float*)d_out;

    cudaFuncSetAttribute(attn_kernel, cudaFuncAttributeMaxDynamicSharedMemorySize, ATTN_SMEM);

    const int N4 = 4096 * 512 / 4;
    dim3 cgrid((N4 + 255) / 256, 3), cblk(256);
    dim3 mgrid(16, 16, 6), mblk(32, 8);

    conv_misc<<<mgrid, mblk>>>(Wq, Wk, Wv, Wo, rel);
    conv_act3<<<cgrid, cblk>>>(queries, keys, values, N4);

    dim3 qkvgrid(8, 64, 3), gblk(128);
    gemm_qkv<<<qkvgrid, gblk>>>();

    dim3 ga(16, 32), tb(256);
    attn_kernel<<<ga, tb, ATTN_SMEM>>>();

    dim3 ogrid(8, 64);
    gemm_out<<<ogrid, gblk>>>(out);
}